// round 4
// baseline (speedup 1.0000x reference)
#include <cuda_runtime.h>
#include <math.h>

#define BB 32
#define NN 1024
#define KNN 20
#define RTOT (BB*NN)          // 32768 rows
#define NEG_SLOPE 0.2f
#define EPS 1e-5f

// ---------------- static scratch (allocation-free rule) ----------------
__device__ __align__(256) float g_pd[(size_t)BB*NN*NN];     // 128 MB
__device__ __align__(256) int   g_idx[(size_t)RTOT*KNN];
__device__ __align__(256) float g_p[(size_t)RTOT*256];
__device__ __align__(256) float g_q[(size_t)RTOT*256];
__device__ __align__(256) float g_hmax[(size_t)RTOT*256];
__device__ __align__(256) float g_cat[(size_t)RTOT*512];
__device__ __align__(256) float g_wq[1024*512];
__device__ __align__(256) float g_xx[RTOT];
__device__ __align__(256) float g_sum[1024];
__device__ __align__(256) float g_sumsq[1024];
__device__ __align__(256) float g_bmax[RTOT];

// ---------------- f32x2 helpers ----------------
__device__ __forceinline__ void fma2(unsigned long long &acc,
                                     unsigned long long a, unsigned long long b) {
    asm("fma.rn.f32x2 %0, %1, %2, %0;" : "+l"(acc) : "l"(a), "l"(b));
}
__device__ __forceinline__ unsigned long long dup2(float v) {
    unsigned long long r;
    asm("mov.b64 %0, {%1, %1};" : "=l"(r) : "f"(v));
    return r;
}
__device__ __forceinline__ float2 unpack2(unsigned long long v) {
    float lo, hi;
    asm("mov.b64 {%0, %1}, %2;" : "=f"(lo), "=f"(hi) : "l"(v));
    return make_float2(lo, hi);
}

__device__ __forceinline__ void atomicMaxFloat(float* addr, float val) {
    int old = __float_as_int(*addr);
    while (__int_as_float(old) < val) {
        int assumed = old;
        old = atomicCAS((int*)addr, assumed, __float_as_int(val));
        if (old == assumed) break;
    }
}

// ---------------- warp top-20 over 32x32 register tile ----------------
__device__ __forceinline__ void warp_top20(float (&vals)[32], int lane, int* orow) {
    unsigned rm = 0;
    float bv = vals[0]; int bslot = 0;
    #pragma unroll
    for (int j = 1; j < 32; j++) { float v = vals[j]; if (v > bv) { bv = v; bslot = j; } }
    for (int it = 0; it < KNN; it++) {
        float cv = bv;
        int ci = (bslot >= 0) ? (bslot*32 + lane) : 0x7fffffff;
        if (bslot < 0) cv = -INFINITY;
        #pragma unroll
        for (int s = 16; s > 0; s >>= 1) {
            float ov = __shfl_xor_sync(0xffffffffu, cv, s);
            int   oi = __shfl_xor_sync(0xffffffffu, ci, s);
            if (ov > cv || (ov == cv && oi < ci)) { cv = ov; ci = oi; }
        }
        if (lane == 0) orow[it] = ci;
        if ((ci & 31) == lane) {
            rm |= 1u << (ci >> 5);
            bv = -INFINITY; bslot = -1;
            #pragma unroll
            for (int j = 0; j < 32; j++) {
                if (!((rm >> j) & 1u)) {
                    float v = vals[j];
                    if (v > bv) { bv = v; bslot = j; }
                }
            }
        }
    }
}

// ---------------- kernels ----------------

__global__ void k_xx(const float* __restrict__ F, int fs, int C, float* __restrict__ xx) {
    int r = blockIdx.x*blockDim.x + threadIdx.x;
    if (r >= RTOT) return;
    const float* f = F + (size_t)r*fs;
    float s = 0.f;
    for (int c = 0; c < C; c++) { float v = f[c]; s += v*v; }
    xx[r] = s;
}

// fused layer-1 KNN: C=3, distances computed on the fly from shared x
__global__ void k_knn3(const float* __restrict__ x, int* __restrict__ idx) {
    __shared__ float sx[NN], sy[NN], sz[NN];
    int b = blockIdx.y;
    const float* xb = x + (size_t)b*NN*3;
    int tid = threadIdx.x;
    for (int i = tid; i < NN; i += 256) {
        sx[i] = xb[i*3+0]; sy[i] = xb[i*3+1]; sz[i] = xb[i*3+2];
    }
    __syncthreads();
    int warp = tid >> 5, lane = tid & 31;
    int n = blockIdx.x*8 + warp;
    float xnx = sx[n], xny = sy[n], xnz = sz[n];
    float xxn = xnx*xnx; xxn += xny*xny; xxn += xnz*xnz;
    float vals[32];
    #pragma unroll
    for (int j = 0; j < 32; j++) {
        int m = j*32 + lane;
        float mx = sx[m], my = sy[m], mz = sz[m];
        float inner = xnx*mx; inner += xny*my; inner += xnz*mz;
        float xxm = mx*mx; xxm += my*my; xxm += mz*mz;
        vals[j] = 2.f*inner - xxn - xxm;
    }
    warp_top20(vals, lane, idx + (size_t)(b*NN + n)*KNN);
}

// fast pairwise GEMM (FFMA2, double-buffered): pd[b,n,m] = 2<F_n,F_m> - xx_n - xx_m
__global__ void k_pair_f(const float* __restrict__ F, int fs, int Kdim,
                         const float* __restrict__ xx, float* __restrict__ pd) {
    __shared__ float As[2][16][132];
    __shared__ float Ws[2][16][68];
    int b = blockIdx.z;
    const float* Fb = F + (size_t)b*NN*fs;
    const float* xb = xx + b*NN;
    int tid = threadIdx.x;
    int tx = tid & 15, ty = tid >> 4;
    int n0 = blockIdx.x*128, m0 = blockIdx.y*64;
    int r0 = tid >> 2, kc = (tid & 3)*4;
    const float* Ar0 = Fb + (size_t)(n0 + r0)*fs + kc;
    const float* Ar1 = Fb + (size_t)(n0 + 64 + r0)*fs + kc;
    const float* Wr  = Fb + (size_t)(m0 + r0)*fs + kc;
    unsigned long long acc[4][4];
    #pragma unroll
    for (int i = 0; i < 4; i++)
        #pragma unroll
        for (int j = 0; j < 4; j++) acc[i][j] = 0ULL;

    float4 a0 = *(const float4*)(Ar0);
    float4 a1 = *(const float4*)(Ar1);
    float4 w0 = *(const float4*)(Wr);
    As[0][kc+0][r0] = a0.x; As[0][kc+1][r0] = a0.y; As[0][kc+2][r0] = a0.z; As[0][kc+3][r0] = a0.w;
    As[0][kc+0][64+r0] = a1.x; As[0][kc+1][64+r0] = a1.y; As[0][kc+2][64+r0] = a1.z; As[0][kc+3][64+r0] = a1.w;
    Ws[0][kc+0][r0] = w0.x; Ws[0][kc+1][r0] = w0.y; Ws[0][kc+2][r0] = w0.z; Ws[0][kc+3][r0] = w0.w;
    __syncthreads();
    int buf = 0;
    for (int k0 = 16; k0 <= Kdim; k0 += 16) {
        bool more = (k0 < Kdim);
        if (more) {
            a0 = *(const float4*)(Ar0 + k0);
            a1 = *(const float4*)(Ar1 + k0);
            w0 = *(const float4*)(Wr  + k0);
        }
        float (*cA)[132] = As[buf];
        float (*cW)[68]  = Ws[buf];
        #pragma unroll
        for (int kk = 0; kk < 16; kk++) {
            ulonglong2 aLo = *(const ulonglong2*)&cA[kk][ty*8];
            ulonglong2 aHi = *(const ulonglong2*)&cA[kk][ty*8+4];
            float4 bv = *(const float4*)&cW[kk][tx*4];
            unsigned long long ap[4] = {aLo.x, aLo.y, aHi.x, aHi.y};
            unsigned long long bp[4] = {dup2(bv.x), dup2(bv.y), dup2(bv.z), dup2(bv.w)};
            #pragma unroll
            for (int i = 0; i < 4; i++)
                #pragma unroll
                for (int j = 0; j < 4; j++) fma2(acc[i][j], ap[i], bp[j]);
        }
        if (more) {
            int nb = buf ^ 1;
            As[nb][kc+0][r0] = a0.x; As[nb][kc+1][r0] = a0.y; As[nb][kc+2][r0] = a0.z; As[nb][kc+3][r0] = a0.w;
            As[nb][kc+0][64+r0] = a1.x; As[nb][kc+1][64+r0] = a1.y; As[nb][kc+2][64+r0] = a1.z; As[nb][kc+3][64+r0] = a1.w;
            Ws[nb][kc+0][r0] = w0.x; Ws[nb][kc+1][r0] = w0.y; Ws[nb][kc+2][r0] = w0.z; Ws[nb][kc+3][r0] = w0.w;
        }
        __syncthreads();
        buf ^= 1;
    }
    float xm[4];
    #pragma unroll
    for (int j = 0; j < 4; j++) xm[j] = xb[m0 + tx*4 + j];
    float* prow = pd + (size_t)b*NN*NN;
    #pragma unroll
    for (int ip = 0; ip < 4; ip++) {
        float2 c0 = unpack2(acc[ip][0]);
        float2 c1 = unpack2(acc[ip][1]);
        float2 c2 = unpack2(acc[ip][2]);
        float2 c3 = unpack2(acc[ip][3]);
        int n = n0 + ty*8 + ip*2;
        float xn0 = xb[n], xn1 = xb[n+1];
        *(float4*)(prow + (size_t)n*NN + m0 + tx*4) =
            make_float4(2.f*c0.x - xn0 - xm[0], 2.f*c1.x - xn0 - xm[1],
                        2.f*c2.x - xn0 - xm[2], 2.f*c3.x - xn0 - xm[3]);
        *(float4*)(prow + (size_t)(n+1)*NN + m0 + tx*4) =
            make_float4(2.f*c0.y - xn1 - xm[0], 2.f*c1.y - xn1 - xm[1],
                        2.f*c2.y - xn1 - xm[2], 2.f*c3.y - xn1 - xm[3]);
    }
}

// warp-per-row top-20 from precomputed pd
__global__ void k_topk_w(const float* __restrict__ pd, int* __restrict__ idx) {
    int warp = threadIdx.x >> 5;
    int lane = threadIdx.x & 31;
    int row = blockIdx.x*8 + warp;
    const float* prow = pd + (size_t)row*NN;
    float vals[32];
    #pragma unroll
    for (int j = 0; j < 32; j++) vals[j] = prow[j*32 + lane];
    warp_top20(vals, lane, idx + (size_t)row*KNN);
}

__global__ void k_wq(const float* __restrict__ W, int C, int O, float* __restrict__ wq) {
    int i = blockIdx.x*blockDim.x + threadIdx.x;
    if (i >= O*C) return;
    int o = i / C, c = i - o*C;
    wq[i] = W[(size_t)o*2*C + C + c] - W[(size_t)o*2*C + c];
}

// generic slow sgemm (layer 1, K=3)
__global__ void k_sgemm(const float* __restrict__ A, int lda,
                        const float* __restrict__ Bw, int ldb,
                        float* __restrict__ Cout, int Kdim, int O) {
    __shared__ float As[16][65], Ws[16][65];
    int tx = threadIdx.x, ty = threadIdx.y;
    int tid = ty*16 + tx;
    int m0 = blockIdx.x*64, o0 = blockIdx.y*64;
    float acc[4][4];
    #pragma unroll
    for (int i = 0; i < 4; i++)
        #pragma unroll
        for (int j = 0; j < 4; j++) acc[i][j] = 0.f;
    for (int k0 = 0; k0 < Kdim; k0 += 16) {
        #pragma unroll
        for (int r = 0; r < 4; r++) {
            int i  = tid + r*256;
            int kk = i & 15, mm = i >> 4;
            As[kk][mm] = (k0+kk < Kdim) ? A[(size_t)(m0+mm)*lda + k0+kk] : 0.f;
            Ws[kk][mm] = (k0+kk < Kdim) ? Bw[(size_t)(o0+mm)*ldb + k0+kk] : 0.f;
        }
        __syncthreads();
        #pragma unroll
        for (int kk = 0; kk < 16; kk++) {
            float a[4], bfr[4];
            #pragma unroll
            for (int i = 0; i < 4; i++) a[i] = As[kk][ty*4 + i];
            #pragma unroll
            for (int j = 0; j < 4; j++) bfr[j] = Ws[kk][tx*4 + j];
            #pragma unroll
            for (int i = 0; i < 4; i++)
                #pragma unroll
                for (int j = 0; j < 4; j++) acc[i][j] += a[i]*bfr[j];
        }
        __syncthreads();
    }
    #pragma unroll
    for (int i = 0; i < 4; i++)
        #pragma unroll
        for (int j = 0; j < 4; j++)
            Cout[(size_t)(m0 + ty*4 + i)*O + o0 + tx*4 + j] = acc[i][j];
}

// fast sgemm (FFMA2, double-buffered): Cout[m,o] = sum_k A[m,k]*Bw[o,k]
__global__ void k_sgemm_f(const float* __restrict__ A, int lda,
                          const float* __restrict__ Bw, int ldb,
                          float* __restrict__ Cout, int ldc, int Kdim) {
    __shared__ float As[2][16][132];
    __shared__ float Ws[2][16][68];
    int tid = threadIdx.x;
    int tx = tid & 15, ty = tid >> 4;
    int m0 = blockIdx.x*128, o0 = blockIdx.y*64;
    int r0 = tid >> 2, kc = (tid & 3)*4;
    const float* Ar0 = A  + (size_t)(m0 + r0)*lda + kc;
    const float* Ar1 = A  + (size_t)(m0 + 64 + r0)*lda + kc;
    const float* Wr  = Bw + (size_t)(o0 + r0)*ldb + kc;
    unsigned long long acc[4][4];
    #pragma unroll
    for (int i = 0; i < 4; i++)
        #pragma unroll
        for (int j = 0; j < 4; j++) acc[i][j] = 0ULL;

    float4 a0 = *(const float4*)(Ar0);
    float4 a1 = *(const float4*)(Ar1);
    float4 w0 = *(const float4*)(Wr);
    As[0][kc+0][r0] = a0.x; As[0][kc+1][r0] = a0.y; As[0][kc+2][r0] = a0.z; As[0][kc+3][r0] = a0.w;
    As[0][kc+0][64+r0] = a1.x; As[0][kc+1][64+r0] = a1.y; As[0][kc+2][64+r0] = a1.z; As[0][kc+3][64+r0] = a1.w;
    Ws[0][kc+0][r0] = w0.x; Ws[0][kc+1][r0] = w0.y; Ws[0][kc+2][r0] = w0.z; Ws[0][kc+3][r0] = w0.w;
    __syncthreads();
    int buf = 0;
    for (int k0 = 16; k0 <= Kdim; k0 += 16) {
        bool more = (k0 < Kdim);
        if (more) {
            a0 = *(const float4*)(Ar0 + k0);
            a1 = *(const float4*)(Ar1 + k0);
            w0 = *(const float4*)(Wr  + k0);
        }
        float (*cA)[132] = As[buf];
        float (*cW)[68]  = Ws[buf];
        #pragma unroll
        for (int kk = 0; kk < 16; kk++) {
            ulonglong2 aLo = *(const ulonglong2*)&cA[kk][ty*8];
            ulonglong2 aHi = *(const ulonglong2*)&cA[kk][ty*8+4];
            float4 bv = *(const float4*)&cW[kk][tx*4];
            unsigned long long ap[4] = {aLo.x, aLo.y, aHi.x, aHi.y};
            unsigned long long bp[4] = {dup2(bv.x), dup2(bv.y), dup2(bv.z), dup2(bv.w)};
            #pragma unroll
            for (int i = 0; i < 4; i++)
                #pragma unroll
                for (int j = 0; j < 4; j++) fma2(acc[i][j], ap[i], bp[j]);
        }
        if (more) {
            int nb = buf ^ 1;
            As[nb][kc+0][r0] = a0.x; As[nb][kc+1][r0] = a0.y; As[nb][kc+2][r0] = a0.z; As[nb][kc+3][r0] = a0.w;
            As[nb][kc+0][64+r0] = a1.x; As[nb][kc+1][64+r0] = a1.y; As[nb][kc+2][64+r0] = a1.z; As[nb][kc+3][64+r0] = a1.w;
            Ws[nb][kc+0][r0] = w0.x; Ws[nb][kc+1][r0] = w0.y; Ws[nb][kc+2][r0] = w0.z; Ws[nb][kc+3][r0] = w0.w;
        }
        __syncthreads();
        buf ^= 1;
    }
    #pragma unroll
    for (int ip = 0; ip < 4; ip++) {
        float2 c0 = unpack2(acc[ip][0]);
        float2 c1 = unpack2(acc[ip][1]);
        float2 c2 = unpack2(acc[ip][2]);
        float2 c3 = unpack2(acc[ip][3]);
        int mrow = m0 + ty*8 + ip*2;
        *(float4*)(Cout + (size_t)mrow*ldc + o0 + tx*4) =
            make_float4(c0.x, c1.x, c2.x, c3.x);
        *(float4*)(Cout + (size_t)(mrow+1)*ldc + o0 + tx*4) =
            make_float4(c0.y, c1.y, c2.y, c3.y);
    }
}

// layer-5 GEMM with fused max/sum/sumsq reduction epilogue (no C write)
__global__ void k_sgemm5(const float* __restrict__ A, const float* __restrict__ Bw,
                         float* __restrict__ bmax, float* __restrict__ sum,
                         float* __restrict__ sumsq) {
    const int lda = 512, ldb = 512, Kdim = 512;
    __shared__ float As[2][16][132];
    __shared__ float Ws[2][16][68];
    __shared__ float red[3][64][17];
    int tid = threadIdx.x;
    int tx = tid & 15, ty = tid >> 4;
    int m0 = blockIdx.x*128, o0 = blockIdx.y*64;
    int r0 = tid >> 2, kc = (tid & 3)*4;
    const float* Ar0 = A  + (size_t)(m0 + r0)*lda + kc;
    const float* Ar1 = A  + (size_t)(m0 + 64 + r0)*lda + kc;
    const float* Wr  = Bw + (size_t)(o0 + r0)*ldb + kc;
    unsigned long long acc[4][4];
    #pragma unroll
    for (int i = 0; i < 4; i++)
        #pragma unroll
        for (int j = 0; j < 4; j++) acc[i][j] = 0ULL;

    float4 a0 = *(const float4*)(Ar0);
    float4 a1 = *(const float4*)(Ar1);
    float4 w0 = *(const float4*)(Wr);
    As[0][kc+0][r0] = a0.x; As[0][kc+1][r0] = a0.y; As[0][kc+2][r0] = a0.z; As[0][kc+3][r0] = a0.w;
    As[0][kc+0][64+r0] = a1.x; As[0][kc+1][64+r0] = a1.y; As[0][kc+2][64+r0] = a1.z; As[0][kc+3][64+r0] = a1.w;
    Ws[0][kc+0][r0] = w0.x; Ws[0][kc+1][r0] = w0.y; Ws[0][kc+2][r0] = w0.z; Ws[0][kc+3][r0] = w0.w;
    __syncthreads();
    int buf = 0;
    for (int k0 = 16; k0 <= Kdim; k0 += 16) {
        bool more = (k0 < Kdim);
        if (more) {
            a0 = *(const float4*)(Ar0 + k0);
            a1 = *(const float4*)(Ar1 + k0);
            w0 = *(const float4*)(Wr  + k0);
        }
        float (*cA)[132] = As[buf];
        float (*cW)[68]  = Ws[buf];
        #pragma unroll
        for (int kk = 0; kk < 16; kk++) {
            ulonglong2 aLo = *(const ulonglong2*)&cA[kk][ty*8];
            ulonglong2 aHi = *(const ulonglong2*)&cA[kk][ty*8+4];
            float4 bv = *(const float4*)&cW[kk][tx*4];
            unsigned long long ap[4] = {aLo.x, aLo.y, aHi.x, aHi.y};
            unsigned long long bp[4] = {dup2(bv.x), dup2(bv.y), dup2(bv.z), dup2(bv.w)};
            #pragma unroll
            for (int i = 0; i < 4; i++)
                #pragma unroll
                for (int j = 0; j < 4; j++) fma2(acc[i][j], ap[i], bp[j]);
        }
        if (more) {
            int nb = buf ^ 1;
            As[nb][kc+0][r0] = a0.x; As[nb][kc+1][r0] = a0.y; As[nb][kc+2][r0] = a0.z; As[nb][kc+3][r0] = a0.w;
            As[nb][kc+0][64+r0] = a1.x; As[nb][kc+1][64+r0] = a1.y; As[nb][kc+2][64+r0] = a1.z; As[nb][kc+3][64+r0] = a1.w;
            Ws[nb][kc+0][r0] = w0.x; Ws[nb][kc+1][r0] = w0.y; Ws[nb][kc+2][r0] = w0.z; Ws[nb][kc+3][r0] = w0.w;
        }
        __syncthreads();
        buf ^= 1;
    }
    // fused reduction: per-column (o) max over 128 rows + sum + sumsq
    float cmax[4], csum[4], csq[4];
    #pragma unroll
    for (int j = 0; j < 4; j++) { cmax[j] = -INFINITY; csum[j] = 0.f; csq[j] = 0.f; }
    #pragma unroll
    for (int ip = 0; ip < 4; ip++) {
        #pragma unroll
        for (int j = 0; j < 4; j++) {
            float2 c = unpack2(acc[ip][j]);
            cmax[j] = fmaxf(cmax[j], fmaxf(c.x, c.y));
            csum[j] += c.x + c.y;
            csq[j]  += c.x*c.x + c.y*c.y;
        }
    }
    #pragma unroll
    for (int j = 0; j < 4; j++) {
        red[0][tx*4+j][ty] = cmax[j];
        red[1][tx*4+j][ty] = csum[j];
        red[2][tx*4+j][ty] = csq[j];
    }
    __syncthreads();
    if (tid < 64) {
        float m = -INFINITY, s = 0.f, s2 = 0.f;
        #pragma unroll
        for (int t = 0; t < 16; t++) {
            m = fmaxf(m, red[0][tid][t]);
            s  += red[1][tid][t];
            s2 += red[2][tid][t];
        }
        int b = m0 >> 10;
        int o = o0 + tid;
        atomicMaxFloat(&bmax[b*1024 + o], m);
        atomicAdd(&sum[o], s);
        atomicAdd(&sumsq[o], s2);
    }
}

__global__ void k_zero(float* a, float* b) { int t = threadIdx.x; a[t] = 0.f; b[t] = 0.f; }

__global__ void k_init5(float* sum, float* sumsq, float* bmax) {
    int t = blockIdx.x*blockDim.x + threadIdx.x;   // 32768
    if (t < 1024) { sum[t] = 0.f; sumsq[t] = 0.f; }
    bmax[t] = -INFINITY;
}

__global__ void k_gather(const float* __restrict__ p, const float* __restrict__ q,
                         const int* __restrict__ idx, float* __restrict__ hmax,
                         float* __restrict__ sum, float* __restrict__ sumsq, int O) {
    int o  = threadIdx.x;
    int r0 = blockIdx.x*32;
    int b  = r0 >> 10;
    __shared__ int sidx[32*KNN];
    for (int i = o; i < 32*KNN; i += blockDim.x) sidx[i] = idx[(size_t)r0*KNN + i];
    __syncthreads();
    const float* pb = p + (size_t)b*NN*O;
    float s = 0.f, s2 = 0.f;
    for (int n = 0; n < 32; n++) {
        int row = r0 + n;
        float cq = q[(size_t)row*O + o];
        float mx = -INFINITY;
        #pragma unroll
        for (int k = 0; k < KNN; k++) {
            float v = pb[(size_t)sidx[n*KNN + k]*O + o];
            mx = fmaxf(mx, v);
            float h = v + cq;
            s += h; s2 += h*h;
        }
        hmax[(size_t)row*O + o] = mx + cq;
    }
    atomicAdd(&sum[o], s);
    atomicAdd(&sumsq[o], s2);
}

__global__ void k_bn(const float* __restrict__ hmax, const float* __restrict__ sum,
                     const float* __restrict__ sumsq,
                     const float* __restrict__ gamma, const float* __restrict__ beta,
                     float* __restrict__ out, int O, int os, float invCnt) {
    int e = blockIdx.x*blockDim.x + threadIdx.x;
    int row = e / O, o = e - row*O;
    float mean = sum[o]*invCnt;
    float var  = sumsq[o]*invCnt - mean*mean;
    float hn = (hmax[e] - mean)*rsqrtf(var + EPS)*gamma[o] + beta[o];
    out[(size_t)row*os + o] = hn >= 0.f ? hn : NEG_SLOPE*hn;
}

__global__ void k_final(const float* __restrict__ bmax, const float* __restrict__ sum,
                        const float* __restrict__ sumsq,
                        const float* __restrict__ gamma, const float* __restrict__ beta,
                        float* __restrict__ out) {
    int e = blockIdx.x*blockDim.x + threadIdx.x;   // 32768
    int o = e & 1023;
    float invCnt = 1.f/32768.f;
    float mean = sum[o]*invCnt;
    float var  = sumsq[o]*invCnt - mean*mean;
    float hn = (bmax[e] - mean)*rsqrtf(var + EPS)*gamma[o] + beta[o];
    out[e] = hn >= 0.f ? hn : NEG_SLOPE*hn;
}

// ---------------- host driver ----------------

static void edge_layer_fast(const float* F, int fs, int C, int O,
                            const float* W, const float* wq,
                            const float* ga, const float* be,
                            float* pd, int* idx, float* p, float* q, float* hmax,
                            float* xx, float* sum, float* sumsq, float* catOut) {
    k_xx<<<RTOT/256, 256>>>(F, fs, C, xx);
    k_pair_f<<<dim3(8, 16, 32), 256>>>(F, fs, C, xx, pd);
    k_topk_w<<<RTOT/8, 256>>>(pd, idx);
    k_sgemm_f<<<dim3(RTOT/128, O/64), 256>>>(F, fs, W,  2*C, p, O, C);
    k_sgemm_f<<<dim3(RTOT/128, O/64), 256>>>(F, fs, wq, C,   q, O, C);
    k_zero<<<1, 1024>>>(sum, sumsq);
    k_gather<<<RTOT/32, O>>>(p, q, idx, hmax, sum, sumsq, O);
    k_bn<<<(RTOT*O)/256, 256>>>(hmax, sum, sumsq, ga, be, catOut, O, 512,
                                1.f/((float)RTOT*KNN));
}

extern "C" void kernel_launch(void* const* d_in, const int* in_sizes, int n_in,
                              void* d_out, int out_size) {
    const float* x = (const float*)d_in[0];
    const float* W[5]; const float* ga[5]; const float* be[5];
    for (int i = 0; i < 5; i++) {
        W[i]  = (const float*)d_in[1 + 3*i];
        ga[i] = (const float*)d_in[2 + 3*i];
        be[i] = (const float*)d_in[3 + 3*i];
    }

    float *pd, *p, *q, *hmax, *cat, *wq, *xx, *sum, *sumsq, *bmax;
    int *idx;
    cudaGetSymbolAddress((void**)&pd,    g_pd);
    cudaGetSymbolAddress((void**)&idx,   g_idx);
    cudaGetSymbolAddress((void**)&p,     g_p);
    cudaGetSymbolAddress((void**)&q,     g_q);
    cudaGetSymbolAddress((void**)&hmax,  g_hmax);
    cudaGetSymbolAddress((void**)&cat,   g_cat);
    cudaGetSymbolAddress((void**)&wq,    g_wq);
    cudaGetSymbolAddress((void**)&xx,    g_xx);
    cudaGetSymbolAddress((void**)&sum,   g_sum);
    cudaGetSymbolAddress((void**)&sumsq, g_sumsq);
    cudaGetSymbolAddress((void**)&bmax,  g_bmax);

    // wq slices (hoisted — only depend on W inputs)
    float* wq1 = wq;                 // 64*3
    float* wq2 = wq + 4096;          // 64*64
    float* wq3 = wq + 4096 + 4096;   // 128*64
    float* wq4 = wq + 4096 + 4096 + 8192;  // 256*128
    k_wq<<<(64*3   + 255)/256, 256>>>(W[0], 3,   64,  wq1);
    k_wq<<<(64*64  + 255)/256, 256>>>(W[1], 64,  64,  wq2);
    k_wq<<<(128*64 + 255)/256, 256>>>(W[2], 64,  128, wq3);
    k_wq<<<(256*128+ 255)/256, 256>>>(W[3], 128, 256, wq4);

    // ---- layer 1 (C=3): fused knn, slow tiny GEMMs ----
    k_knn3<<<dim3(128, 32), 256>>>(x, idx);
    k_sgemm<<<dim3(RTOT/64, 1), dim3(16,16)>>>(x, 3, W[0], 6, p,   3, 64);
    k_sgemm<<<dim3(RTOT/64, 1), dim3(16,16)>>>(x, 3, wq1,  3, q,   3, 64);
    k_zero<<<1, 1024>>>(sum, sumsq);
    k_gather<<<RTOT/32, 64>>>(p, q, idx, hmax, sum, sumsq, 64);
    k_bn<<<(RTOT*64)/256, 256>>>(hmax, sum, sumsq, ga[0], be[0], cat + 0, 64, 512,
                                 1.f/((float)RTOT*KNN));

    // ---- layers 2-4 ----
    edge_layer_fast(cat+0,   512, 64,  64,  W[1], wq2, ga[1], be[1],
                    pd, idx, p, q, hmax, xx, sum, sumsq, cat + 64);
    edge_layer_fast(cat+64,  512, 64,  128, W[2], wq3, ga[2], be[2],
                    pd, idx, p, q, hmax, xx, sum, sumsq, cat + 128);
    edge_layer_fast(cat+128, 512, 128, 256, W[3], wq4, ga[3], be[3],
                    pd, idx, p, q, hmax, xx, sum, sumsq, cat + 256);

    // ---- layer 5: fused GEMM + max/stats reduction, then BN+lrelu ----
    k_init5<<<128, 256>>>(sum, sumsq, bmax);
    k_sgemm5<<<dim3(RTOT/128, 1024/64), 256>>>(cat, W[4], bmax, sum, sumsq);
    k_final<<<RTOT/256, 256>>>(bmax, sum, sumsq, ga[4], be[4], (float*)d_out);
}

// round 5
// speedup vs baseline: 1.5750x; 1.5750x over previous
#include <cuda_runtime.h>
#include <math.h>

#define BB 32
#define NN 1024
#define KNN 20
#define RTOT (BB*NN)          // 32768 rows
#define NEG_SLOPE 0.2f
#define EPS 1e-5f

// ---------------- static scratch (allocation-free rule) ----------------
__device__ __align__(256) float g_pd[(size_t)BB*NN*NN];     // 128 MB
__device__ __align__(256) int   g_idx[(size_t)RTOT*KNN];
__device__ __align__(256) float g_pq[(size_t)RTOT*512];     // packed [p|q], max 2O=512
__device__ __align__(256) float g_hmax[(size_t)RTOT*256];
__device__ __align__(256) float g_cat[(size_t)RTOT*512];
__device__ __align__(256) float g_wc[1024*512];
__device__ __align__(256) float g_xx[RTOT];
__device__ __align__(256) float g_sum[1024];
__device__ __align__(256) float g_sumsq[1024];
__device__ __align__(256) float g_bmax[RTOT];

// ---------------- f32x2 helpers ----------------
__device__ __forceinline__ void fma2(unsigned long long &acc,
                                     unsigned long long a, unsigned long long b) {
    asm("fma.rn.f32x2 %0, %1, %2, %0;" : "+l"(acc) : "l"(a), "l"(b));
}
__device__ __forceinline__ unsigned long long dup2(float v) {
    unsigned long long r;
    asm("mov.b64 %0, {%1, %1};" : "=l"(r) : "f"(v));
    return r;
}
__device__ __forceinline__ float2 unpack2(unsigned long long v) {
    float lo, hi;
    asm("mov.b64 {%0, %1}, %2;" : "=f"(lo), "=f"(hi) : "l"(v));
    return make_float2(lo, hi);
}

// ---------------- shared GEMM building blocks (static smem indices) -----
__device__ __forceinline__ void store_tile(float (&As)[16][132], float (&Ws)[16][68],
                                           int r0, int kc,
                                           const float4& a0, const float4& a1,
                                           const float4& w0) {
    As[kc+0][r0] = a0.x; As[kc+1][r0] = a0.y; As[kc+2][r0] = a0.z; As[kc+3][r0] = a0.w;
    As[kc+0][64+r0] = a1.x; As[kc+1][64+r0] = a1.y; As[kc+2][64+r0] = a1.z; As[kc+3][64+r0] = a1.w;
    Ws[kc+0][r0] = w0.x; Ws[kc+1][r0] = w0.y; Ws[kc+2][r0] = w0.z; Ws[kc+3][r0] = w0.w;
}

__device__ __forceinline__ void gemm_step16(const float (&As)[16][132], const float (&Ws)[16][68],
                                            int ty, int tx, unsigned long long (&acc)[4][4]) {
    #pragma unroll
    for (int kk = 0; kk < 16; kk++) {
        ulonglong2 aLo = *(const ulonglong2*)&As[kk][ty*8];
        ulonglong2 aHi = *(const ulonglong2*)&As[kk][ty*8+4];
        float4 bv = *(const float4*)&Ws[kk][tx*4];
        unsigned long long ap[4] = {aLo.x, aLo.y, aHi.x, aHi.y};
        unsigned long long bp[4] = {dup2(bv.x), dup2(bv.y), dup2(bv.z), dup2(bv.w)};
        #pragma unroll
        for (int i = 0; i < 4; i++)
            #pragma unroll
            for (int j = 0; j < 4; j++) fma2(acc[i][j], ap[i], bp[j]);
    }
}

// Double-buffered mainloop (Kdim % 32 == 0). One sync per 16-k step,
// static buffer selection (As0/As1 are distinct smem arrays).
#define GEMM_MAINLOOP(Ar0, Ar1, Wr, Kdim)                                      \
    {                                                                          \
        float4 a0 = *(const float4*)(Ar0);                                     \
        float4 a1 = *(const float4*)(Ar1);                                     \
        float4 w0 = *(const float4*)(Wr);                                      \
        store_tile(As0, Ws0, r0, kc, a0, a1, w0);                              \
        __syncthreads();                                                       \
        int nsteps = (Kdim) >> 4;                                              \
        for (int s = 0; s < nsteps; s += 2) {                                  \
            bool pf1 = (s + 1) < nsteps;                                       \
            if (pf1) {                                                         \
                a0 = *(const float4*)(Ar0 + (s+1)*16);                         \
                a1 = *(const float4*)(Ar1 + (s+1)*16);                         \
                w0 = *(const float4*)(Wr  + (s+1)*16);                         \
            }                                                                  \
            gemm_step16(As0, Ws0, ty, tx, acc);                                \
            if (pf1) store_tile(As1, Ws1, r0, kc, a0, a1, w0);                 \
            __syncthreads();                                                   \
            if (!pf1) break;                                                   \
            bool pf2 = (s + 2) < nsteps;                                       \
            if (pf2) {                                                         \
                a0 = *(const float4*)(Ar0 + (s+2)*16);                         \
                a1 = *(const float4*)(Ar1 + (s+2)*16);                         \
                w0 = *(const float4*)(Wr  + (s+2)*16);                         \
            }                                                                  \
            gemm_step16(As1, Ws1, ty, tx, acc);                                \
            if (pf2) store_tile(As0, Ws0, r0, kc, a0, a1, w0);                 \
            __syncthreads();                                                   \
        }                                                                      \
    }

// ---------------- warp top-20 over 32x32 register tile ----------------
__device__ __forceinline__ void warp_top20(float (&vals)[32], int lane, int* orow) {
    unsigned rm = 0;
    float bv = vals[0]; int bslot = 0;
    #pragma unroll
    for (int j = 1; j < 32; j++) { float v = vals[j]; if (v > bv) { bv = v; bslot = j; } }
    for (int it = 0; it < KNN; it++) {
        float cv = bv;
        int ci = (bslot >= 0) ? (bslot*32 + lane) : 0x7fffffff;
        if (bslot < 0) cv = -INFINITY;
        #pragma unroll
        for (int s = 16; s > 0; s >>= 1) {
            float ov = __shfl_xor_sync(0xffffffffu, cv, s);
            int   oi = __shfl_xor_sync(0xffffffffu, ci, s);
            if (ov > cv || (ov == cv && oi < ci)) { cv = ov; ci = oi; }
        }
        if (lane == 0) orow[it] = ci;
        if ((ci & 31) == lane) {
            rm |= 1u << (ci >> 5);
            bv = -INFINITY; bslot = -1;
            #pragma unroll
            for (int j = 0; j < 32; j++) {
                if (!((rm >> j) & 1u)) {
                    float v = vals[j];
                    if (v > bv) { bv = v; bslot = j; }
                }
            }
        }
    }
}

// ---------------- kernels ----------------

__global__ void k_xx(const float* __restrict__ F, int fs, int C, float* __restrict__ xx) {
    int r = blockIdx.x*blockDim.x + threadIdx.x;
    if (r >= RTOT) return;
    const float* f = F + (size_t)r*fs;
    float s = 0.f;
    for (int c = 0; c < C; c++) { float v = f[c]; s += v*v; }
    xx[r] = s;
}

// fused layer-1 KNN: C=3, distances computed on the fly from shared x
__global__ void k_knn3(const float* __restrict__ x, int* __restrict__ idx) {
    __shared__ float sx[NN], sy[NN], sz[NN];
    int b = blockIdx.y;
    const float* xb = x + (size_t)b*NN*3;
    int tid = threadIdx.x;
    for (int i = tid; i < NN; i += 256) {
        sx[i] = xb[i*3+0]; sy[i] = xb[i*3+1]; sz[i] = xb[i*3+2];
    }
    __syncthreads();
    int warp = tid >> 5, lane = tid & 31;
    int n = blockIdx.x*8 + warp;
    float xnx = sx[n], xny = sy[n], xnz = sz[n];
    float xxn = xnx*xnx; xxn += xny*xny; xxn += xnz*xnz;
    float vals[32];
    #pragma unroll
    for (int j = 0; j < 32; j++) {
        int m = j*32 + lane;
        float mx = sx[m], my = sy[m], mz = sz[m];
        float inner = xnx*mx; inner += xny*my; inner += xnz*mz;
        float xxm = mx*mx; xxm += my*my; xxm += mz*mz;
        vals[j] = 2.f*inner - xxn - xxm;
    }
    warp_top20(vals, lane, idx + (size_t)(b*NN + n)*KNN);
}

// pairwise GEMM (FFMA2, static double buffer): pd[b,n,m] = 2<F_n,F_m> - xx_n - xx_m
__global__ void k_pair_f(const float* __restrict__ F, int fs, int Kdim,
                         const float* __restrict__ xx, float* __restrict__ pd) {
    __shared__ float As0[16][132], Ws0[16][68];
    __shared__ float As1[16][132], Ws1[16][68];
    int b = blockIdx.z;
    const float* Fb = F + (size_t)b*NN*fs;
    const float* xb = xx + b*NN;
    int tid = threadIdx.x;
    int tx = tid & 15, ty = tid >> 4;
    int n0 = blockIdx.x*128, m0 = blockIdx.y*64;
    int r0 = tid >> 2, kc = (tid & 3)*4;
    const float* Ar0 = Fb + (size_t)(n0 + r0)*fs + kc;
    const float* Ar1 = Fb + (size_t)(n0 + 64 + r0)*fs + kc;
    const float* Wr  = Fb + (size_t)(m0 + r0)*fs + kc;
    unsigned long long acc[4][4];
    #pragma unroll
    for (int i = 0; i < 4; i++)
        #pragma unroll
        for (int j = 0; j < 4; j++) acc[i][j] = 0ULL;

    GEMM_MAINLOOP(Ar0, Ar1, Wr, Kdim)

    float xm[4];
    #pragma unroll
    for (int j = 0; j < 4; j++) xm[j] = xb[m0 + tx*4 + j];
    float* prow = pd + (size_t)b*NN*NN;
    #pragma unroll
    for (int ip = 0; ip < 4; ip++) {
        float2 c0 = unpack2(acc[ip][0]);
        float2 c1 = unpack2(acc[ip][1]);
        float2 c2 = unpack2(acc[ip][2]);
        float2 c3 = unpack2(acc[ip][3]);
        int n = n0 + ty*8 + ip*2;
        float xn0 = xb[n], xn1 = xb[n+1];
        *(float4*)(prow + (size_t)n*NN + m0 + tx*4) =
            make_float4(2.f*c0.x - xn0 - xm[0], 2.f*c1.x - xn0 - xm[1],
                        2.f*c2.x - xn0 - xm[2], 2.f*c3.x - xn0 - xm[3]);
        *(float4*)(prow + (size_t)(n+1)*NN + m0 + tx*4) =
            make_float4(2.f*c0.y - xn1 - xm[0], 2.f*c1.y - xn1 - xm[1],
                        2.f*c2.y - xn1 - xm[2], 2.f*c3.y - xn1 - xm[3]);
    }
}

// warp-per-row top-20 from precomputed pd
__global__ void k_topk_w(const float* __restrict__ pd, int* __restrict__ idx) {
    int warp = threadIdx.x >> 5;
    int lane = threadIdx.x & 31;
    int row = blockIdx.x*8 + warp;
    const float* prow = pd + (size_t)row*NN;
    float vals[32];
    #pragma unroll
    for (int j = 0; j < 32; j++) vals[j] = prow[j*32 + lane];
    warp_top20(vals, lane, idx + (size_t)row*KNN);
}

// packed weights: Wc[0..O-1] = Wn, Wc[O..2O-1] = Wctr - Wn  (ld C)
__global__ void k_wpack(const float* __restrict__ W, int C, int O, float* __restrict__ wc) {
    int i = blockIdx.x*blockDim.x + threadIdx.x;
    if (i >= 2*O*C) return;
    int o2 = i / C, c = i - o2*C;
    if (o2 < O) wc[i] = W[(size_t)o2*2*C + c];
    else {
        int o = o2 - O;
        wc[i] = W[(size_t)o*2*C + C + c] - W[(size_t)o*2*C + c];
    }
}

// generic slow sgemm (layer 1, K=3)
__global__ void k_sgemm(const float* __restrict__ A, int lda,
                        const float* __restrict__ Bw, int ldb,
                        float* __restrict__ Cout, int Kdim, int O) {
    __shared__ float As[16][65], Ws[16][65];
    int tx = threadIdx.x, ty = threadIdx.y;
    int tid = ty*16 + tx;
    int m0 = blockIdx.x*64, o0 = blockIdx.y*64;
    float acc[4][4];
    #pragma unroll
    for (int i = 0; i < 4; i++)
        #pragma unroll
        for (int j = 0; j < 4; j++) acc[i][j] = 0.f;
    for (int k0 = 0; k0 < Kdim; k0 += 16) {
        #pragma unroll
        for (int r = 0; r < 4; r++) {
            int i  = tid + r*256;
            int kk = i & 15, mm = i >> 4;
            As[kk][mm] = (k0+kk < Kdim) ? A[(size_t)(m0+mm)*lda + k0+kk] : 0.f;
            Ws[kk][mm] = (k0+kk < Kdim) ? Bw[(size_t)(o0+mm)*ldb + k0+kk] : 0.f;
        }
        __syncthreads();
        #pragma unroll
        for (int kk = 0; kk < 16; kk++) {
            float a[4], bfr[4];
            #pragma unroll
            for (int i = 0; i < 4; i++) a[i] = As[kk][ty*4 + i];
            #pragma unroll
            for (int j = 0; j < 4; j++) bfr[j] = Ws[kk][tx*4 + j];
            #pragma unroll
            for (int i = 0; i < 4; i++)
                #pragma unroll
                for (int j = 0; j < 4; j++) acc[i][j] += a[i]*bfr[j];
        }
        __syncthreads();
    }
    #pragma unroll
    for (int i = 0; i < 4; i++)
        #pragma unroll
        for (int j = 0; j < 4; j++)
            Cout[(size_t)(m0 + ty*4 + i)*O + o0 + tx*4 + j] = acc[i][j];
}

// fast sgemm (FFMA2, static double buffer): Cout[m,o] = sum_k A[m,k]*Bw[o,k]
__global__ void k_sgemm_f(const float* __restrict__ A, int lda,
                          const float* __restrict__ Bw, int ldb,
                          float* __restrict__ Cout, int ldc, int Kdim) {
    __shared__ float As0[16][132], Ws0[16][68];
    __shared__ float As1[16][132], Ws1[16][68];
    int tid = threadIdx.x;
    int tx = tid & 15, ty = tid >> 4;
    int m0 = blockIdx.x*128, o0 = blockIdx.y*64;
    int r0 = tid >> 2, kc = (tid & 3)*4;
    const float* Ar0 = A  + (size_t)(m0 + r0)*lda + kc;
    const float* Ar1 = A  + (size_t)(m0 + 64 + r0)*lda + kc;
    const float* Wr  = Bw + (size_t)(o0 + r0)*ldb + kc;
    unsigned long long acc[4][4];
    #pragma unroll
    for (int i = 0; i < 4; i++)
        #pragma unroll
        for (int j = 0; j < 4; j++) acc[i][j] = 0ULL;

    GEMM_MAINLOOP(Ar0, Ar1, Wr, Kdim)

    #pragma unroll
    for (int ip = 0; ip < 4; ip++) {
        float2 c0 = unpack2(acc[ip][0]);
        float2 c1 = unpack2(acc[ip][1]);
        float2 c2 = unpack2(acc[ip][2]);
        float2 c3 = unpack2(acc[ip][3]);
        int mrow = m0 + ty*8 + ip*2;
        *(float4*)(Cout + (size_t)mrow*ldc + o0 + tx*4) =
            make_float4(c0.x, c1.x, c2.x, c3.x);
        *(float4*)(Cout + (size_t)(mrow+1)*ldc + o0 + tx*4) =
            make_float4(c0.y, c1.y, c2.y, c3.y);
    }
}

__global__ void k_zero(float* a, float* b) { int t = threadIdx.x; a[t] = 0.f; b[t] = 0.f; }

// pq layout: row stride 2O, p at [0,O), q at [O,2O)
__global__ void k_gather(const float* __restrict__ pq, const int* __restrict__ idx,
                         float* __restrict__ hmax,
                         float* __restrict__ sum, float* __restrict__ sumsq, int O) {
    int o  = threadIdx.x;
    int r0 = blockIdx.x*32;
    int b  = r0 >> 10;
    int ld = 2*O;
    __shared__ int sidx[32*KNN];
    for (int i = o; i < 32*KNN; i += blockDim.x) sidx[i] = idx[(size_t)r0*KNN + i];
    __syncthreads();
    const float* pb = pq + (size_t)b*NN*ld;
    float s = 0.f, s2 = 0.f;
    for (int n = 0; n < 32; n++) {
        int row = r0 + n;
        float cq = pq[(size_t)row*ld + O + o];
        float mx = -INFINITY;
        #pragma unroll
        for (int k = 0; k < KNN; k++) {
            float v = pb[(size_t)sidx[n*KNN + k]*ld + o];
            mx = fmaxf(mx, v);
            float h = v + cq;
            s += h; s2 += h*h;
        }
        hmax[(size_t)row*O + o] = mx + cq;
    }
    atomicAdd(&sum[o], s);
    atomicAdd(&sumsq[o], s2);
}

__global__ void k_bn(const float* __restrict__ hmax, const float* __restrict__ sum,
                     const float* __restrict__ sumsq,
                     const float* __restrict__ gamma, const float* __restrict__ beta,
                     float* __restrict__ out, int O, int os, float invCnt) {
    int e = blockIdx.x*blockDim.x + threadIdx.x;
    int row = e / O, o = e - row*O;
    float mean = sum[o]*invCnt;
    float var  = sumsq[o]*invCnt - mean*mean;
    float hn = (hmax[e] - mean)*rsqrtf(var + EPS)*gamma[o] + beta[o];
    out[(size_t)row*os + o] = hn >= 0.f ? hn : NEG_SLOPE*hn;
}

__global__ void k_reduce5(const float* __restrict__ h, float* __restrict__ bmax,
                          float* __restrict__ sum, float* __restrict__ sumsq) {
    int b = blockIdx.x;
    int o = blockIdx.y*256 + threadIdx.x;
    const float* hb = h + (size_t)b*NN*1024;
    float mx = -INFINITY, s = 0.f, s2 = 0.f;
    for (int n = 0; n < NN; n++) {
        float v = hb[(size_t)n*1024 + o];
        mx = fmaxf(mx, v); s += v; s2 += v*v;
    }
    bmax[b*1024 + o] = mx;
    atomicAdd(&sum[o], s);
    atomicAdd(&sumsq[o], s2);
}

__global__ void k_final(const float* __restrict__ bmax, const float* __restrict__ sum,
                        const float* __restrict__ sumsq,
                        const float* __restrict__ gamma, const float* __restrict__ beta,
                        float* __restrict__ out) {
    int e = blockIdx.x*blockDim.x + threadIdx.x;   // 32768
    int o = e & 1023;
    float invCnt = 1.f/32768.f;
    float mean = sum[o]*invCnt;
    float var  = sumsq[o]*invCnt - mean*mean;
    float hn = (bmax[e] - mean)*rsqrtf(var + EPS)*gamma[o] + beta[o];
    out[e] = hn >= 0.f ? hn : NEG_SLOPE*hn;
}

// ---------------- host driver ----------------

static void edge_layer_fast(const float* F, int fs, int C, int O,
                            const float* Wc, const float* ga, const float* be,
                            float* pd, int* idx, float* pq, float* hmax,
                            float* xx, float* sum, float* sumsq, float* catOut) {
    k_xx<<<RTOT/256, 256>>>(F, fs, C, xx);
    k_pair_f<<<dim3(8, 16, 32), 256>>>(F, fs, C, xx, pd);
    k_topk_w<<<RTOT/8, 256>>>(pd, idx);
    k_sgemm_f<<<dim3(RTOT/128, 2*O/64), 256>>>(F, fs, Wc, C, pq, 2*O, C);
    k_zero<<<1, 1024>>>(sum, sumsq);
    k_gather<<<RTOT/32, O>>>(pq, idx, hmax, sum, sumsq, O);
    k_bn<<<(RTOT*O)/256, 256>>>(hmax, sum, sumsq, ga, be, catOut, O, 512,
                                1.f/((float)RTOT*KNN));
}

extern "C" void kernel_launch(void* const* d_in, const int* in_sizes, int n_in,
                              void* d_out, int out_size) {
    const float* x = (const float*)d_in[0];
    const float* W[5]; const float* ga[5]; const float* be[5];
    for (int i = 0; i < 5; i++) {
        W[i]  = (const float*)d_in[1 + 3*i];
        ga[i] = (const float*)d_in[2 + 3*i];
        be[i] = (const float*)d_in[3 + 3*i];
    }

    float *pd, *pq, *hmax, *cat, *wc, *xx, *sum, *sumsq, *bmax;
    int *idx;
    cudaGetSymbolAddress((void**)&pd,    g_pd);
    cudaGetSymbolAddress((void**)&idx,   g_idx);
    cudaGetSymbolAddress((void**)&pq,    g_pq);
    cudaGetSymbolAddress((void**)&hmax,  g_hmax);
    cudaGetSymbolAddress((void**)&cat,   g_cat);
    cudaGetSymbolAddress((void**)&wc,    g_wc);
    cudaGetSymbolAddress((void**)&xx,    g_xx);
    cudaGetSymbolAddress((void**)&sum,   g_sum);
    cudaGetSymbolAddress((void**)&sumsq, g_sumsq);
    cudaGetSymbolAddress((void**)&bmax,  g_bmax);

    // packed weight slices (only depend on W inputs)
    float* wc1 = wc;                       // 128*3   = 384
    float* wc2 = wc1 + 512;                // 128*64  = 8192
    float* wc3 = wc2 + 8192;               // 256*64  = 16384
    float* wc4 = wc3 + 16384;              // 512*128 = 65536
    k_wpack<<<(2*64*3   + 255)/256, 256>>>(W[0], 3,   64,  wc1);
    k_wpack<<<(2*64*64  + 255)/256, 256>>>(W[1], 64,  64,  wc2);
    k_wpack<<<(2*128*64 + 255)/256, 256>>>(W[2], 64,  128, wc3);
    k_wpack<<<(2*256*128+ 255)/256, 256>>>(W[3], 128, 256, wc4);

    // ---- layer 1 (C=3): fused knn, slow tiny GEMM (packed pq, 2O=128) ----
    k_knn3<<<dim3(128, 32), 256>>>(x, idx);
    k_sgemm<<<dim3(RTOT/64, 2), dim3(16,16)>>>(x, 3, wc1, 3, pq, 3, 128);
    k_zero<<<1, 1024>>>(sum, sumsq);
    k_gather<<<RTOT/32, 64>>>(pq, idx, hmax, sum, sumsq, 64);
    k_bn<<<(RTOT*64)/256, 256>>>(hmax, sum, sumsq, ga[0], be[0], cat + 0, 64, 512,
                                 1.f/((float)RTOT*KNN));

    // ---- layers 2-4 ----
    edge_layer_fast(cat+0,   512, 64,  64,  wc2, ga[1], be[1],
                    pd, idx, pq, hmax, xx, sum, sumsq, cat + 64);
    edge_layer_fast(cat+64,  512, 64,  128, wc3, ga[2], be[2],
                    pd, idx, pq, hmax, xx, sum, sumsq, cat + 128);
    edge_layer_fast(cat+128, 512, 128, 256, wc4, ga[3], be[3],
                    pd, idx, pq, hmax, xx, sum, sumsq, cat + 256);

    // ---- layer 5: h = cat @ W5^T (into g_pd), BN over (B,N), lrelu, max over N ----
    k_sgemm_f<<<dim3(RTOT/128, 1024/64), 256>>>(cat, 512, W[4], 512, pd, 1024, 512);
    k_zero<<<1, 1024>>>(sum, sumsq);
    k_reduce5<<<dim3(BB, 4), 256>>>(pd, bmax, sum, sumsq);
    k_final<<<RTOT/256, 256>>>(bmax, sum, sumsq, ga[4], be[4], (float*)d_out);
}

// round 7
// speedup vs baseline: 1.7746x; 1.1267x over previous
#include <cuda_runtime.h>
#include <cuda_bf16.h>
#include <math.h>
#include <stdint.h>

#define BB 32
#define NN 1024
#define KNN 20
#define RTOT (BB*NN)          // 32768 rows
#define NEG_SLOPE 0.2f
#define EPS 1e-5f

// ---------------- static scratch (allocation-free rule) ----------------
__device__ __align__(256) float g_pd[(size_t)BB*NN*NN];     // 128 MB
__device__ __align__(256) int   g_idx[(size_t)RTOT*KNN];
__device__ __align__(256) float g_pq[(size_t)RTOT*512];     // packed [p|q]
__device__ __align__(256) float g_hmax[(size_t)RTOT*256];
__device__ __align__(256) float g_cat[(size_t)RTOT*512];
__device__ __align__(256) float g_wc[1024*512];
__device__ __align__(256) float g_xx[RTOT];
__device__ __align__(256) float g_sum[1024];
__device__ __align__(256) float g_sumsq[1024];
__device__ __align__(256) float g_bmax[RTOT];
__device__ __align__(256) __nv_bfloat16 g_w5h[1024*512];
__device__ __align__(256) __nv_bfloat16 g_w5l[1024*512];

// ---------------- f32x2 helpers ----------------
__device__ __forceinline__ void fma2(unsigned long long &acc,
                                     unsigned long long a, unsigned long long b) {
    asm("fma.rn.f32x2 %0, %1, %2, %0;" : "+l"(acc) : "l"(a), "l"(b));
}
__device__ __forceinline__ unsigned long long dup2(float v) {
    unsigned long long r;
    asm("mov.b64 %0, {%1, %1};" : "=l"(r) : "f"(v));
    return r;
}
__device__ __forceinline__ float2 unpack2(unsigned long long v) {
    float lo, hi;
    asm("mov.b64 {%0, %1}, %2;" : "=f"(lo), "=f"(hi) : "l"(v));
    return make_float2(lo, hi);
}

// ---------------- mma.sync helper (bf16 m16n8k16, fp32 accum) ----------------
__device__ __forceinline__ void mma16816(float* c, const uint32_t* a, const uint32_t* b) {
    asm volatile("mma.sync.aligned.m16n8k16.row.col.f32.bf16.bf16.f32 "
        "{%0,%1,%2,%3}, {%4,%5,%6,%7}, {%8,%9}, {%0,%1,%2,%3};"
        : "+f"(c[0]), "+f"(c[1]), "+f"(c[2]), "+f"(c[3])
        : "r"(a[0]), "r"(a[1]), "r"(a[2]), "r"(a[3]), "r"(b[0]), "r"(b[1]));
}

// ---------------- shared GEMM building blocks (fp32 FFMA2 path) -----
__device__ __forceinline__ void store_tile(float (&As)[16][132], float (&Ws)[16][68],
                                           int r0, int kc,
                                           const float4& a0, const float4& a1,
                                           const float4& w0) {
    As[kc+0][r0] = a0.x; As[kc+1][r0] = a0.y; As[kc+2][r0] = a0.z; As[kc+3][r0] = a0.w;
    As[kc+0][64+r0] = a1.x; As[kc+1][64+r0] = a1.y; As[kc+2][64+r0] = a1.z; As[kc+3][64+r0] = a1.w;
    Ws[kc+0][r0] = w0.x; Ws[kc+1][r0] = w0.y; Ws[kc+2][r0] = w0.z; Ws[kc+3][r0] = w0.w;
}

__device__ __forceinline__ void gemm_step16(const float (&As)[16][132], const float (&Ws)[16][68],
                                            int ty, int tx, unsigned long long (&acc)[4][4]) {
    #pragma unroll
    for (int kk = 0; kk < 16; kk++) {
        ulonglong2 aLo = *(const ulonglong2*)&As[kk][ty*8];
        ulonglong2 aHi = *(const ulonglong2*)&As[kk][ty*8+4];
        float4 bv = *(const float4*)&Ws[kk][tx*4];
        unsigned long long ap[4] = {aLo.x, aLo.y, aHi.x, aHi.y};
        unsigned long long bp[4] = {dup2(bv.x), dup2(bv.y), dup2(bv.z), dup2(bv.w)};
        #pragma unroll
        for (int i = 0; i < 4; i++)
            #pragma unroll
            for (int j = 0; j < 4; j++) fma2(acc[i][j], ap[i], bp[j]);
    }
}

#define GEMM_MAINLOOP(Ar0, Ar1, Wr, Kdim)                                      \
    {                                                                          \
        float4 a0 = *(const float4*)(Ar0);                                     \
        float4 a1 = *(const float4*)(Ar1);                                     \
        float4 w0 = *(const float4*)(Wr);                                      \
        store_tile(As0, Ws0, r0, kc, a0, a1, w0);                              \
        __syncthreads();                                                       \
        int nsteps = (Kdim) >> 4;                                              \
        for (int s = 0; s < nsteps; s += 2) {                                  \
            bool pf1 = (s + 1) < nsteps;                                       \
            if (pf1) {                                                         \
                a0 = *(const float4*)(Ar0 + (s+1)*16);                         \
                a1 = *(const float4*)(Ar1 + (s+1)*16);                         \
                w0 = *(const float4*)(Wr  + (s+1)*16);                         \
            }                                                                  \
            gemm_step16(As0, Ws0, ty, tx, acc);                                \
            if (pf1) store_tile(As1, Ws1, r0, kc, a0, a1, w0);                 \
            __syncthreads();                                                   \
            if (!pf1) break;                                                   \
            bool pf2 = (s + 2) < nsteps;                                       \
            if (pf2) {                                                         \
                a0 = *(const float4*)(Ar0 + (s+2)*16);                         \
                a1 = *(const float4*)(Ar1 + (s+2)*16);                         \
                w0 = *(const float4*)(Wr  + (s+2)*16);                         \
            }                                                                  \
            gemm_step16(As1, Ws1, ty, tx, acc);                                \
            if (pf2) store_tile(As0, Ws0, r0, kc, a0, a1, w0);                 \
            __syncthreads();                                                   \
        }                                                                      \
    }

// ---------------- warp top-20 over 32x32 register tile ----------------
__device__ __forceinline__ void warp_top20(float (&vals)[32], int lane, int* orow) {
    unsigned rm = 0;
    float bv = vals[0]; int bslot = 0;
    #pragma unroll
    for (int j = 1; j < 32; j++) { float v = vals[j]; if (v > bv) { bv = v; bslot = j; } }
    for (int it = 0; it < KNN; it++) {
        float cv = bv;
        int ci = (bslot >= 0) ? (bslot*32 + lane) : 0x7fffffff;
        if (bslot < 0) cv = -INFINITY;
        #pragma unroll
        for (int s = 16; s > 0; s >>= 1) {
            float ov = __shfl_xor_sync(0xffffffffu, cv, s);
            int   oi = __shfl_xor_sync(0xffffffffu, ci, s);
            if (ov > cv || (ov == cv && oi < ci)) { cv = ov; ci = oi; }
        }
        if (lane == 0) orow[it] = ci;
        if ((ci & 31) == lane) {
            rm |= 1u << (ci >> 5);
            bv = -INFINITY; bslot = -1;
            #pragma unroll
            for (int j = 0; j < 32; j++) {
                if (!((rm >> j) & 1u)) {
                    float v = vals[j];
                    if (v > bv) { bv = v; bslot = j; }
                }
            }
        }
    }
}

// ---------------- kernels ----------------

__global__ void k_xx(const float* __restrict__ F, int fs, int C, float* __restrict__ xx) {
    int r = blockIdx.x*blockDim.x + threadIdx.x;
    if (r >= RTOT) return;
    const float* f = F + (size_t)r*fs;
    float s = 0.f;
    for (int c = 0; c < C; c++) { float v = f[c]; s += v*v; }
    xx[r] = s;
}

__global__ void k_knn3(const float* __restrict__ x, int* __restrict__ idx) {
    __shared__ float sx[NN], sy[NN], sz[NN];
    int b = blockIdx.y;
    const float* xb = x + (size_t)b*NN*3;
    int tid = threadIdx.x;
    for (int i = tid; i < NN; i += 256) {
        sx[i] = xb[i*3+0]; sy[i] = xb[i*3+1]; sz[i] = xb[i*3+2];
    }
    __syncthreads();
    int warp = tid >> 5, lane = tid & 31;
    int n = blockIdx.x*8 + warp;
    float xnx = sx[n], xny = sy[n], xnz = sz[n];
    float xxn = xnx*xnx; xxn += xny*xny; xxn += xnz*xnz;
    float vals[32];
    #pragma unroll
    for (int j = 0; j < 32; j++) {
        int m = j*32 + lane;
        float mx = sx[m], my = sy[m], mz = sz[m];
        float inner = xnx*mx; inner += xny*my; inner += xnz*mz;
        float xxm = mx*mx; xxm += my*my; xxm += mz*mz;
        vals[j] = 2.f*inner - xxn - xxm;
    }
    warp_top20(vals, lane, idx + (size_t)(b*NN + n)*KNN);
}

__global__ void k_pair_f(const float* __restrict__ F, int fs, int Kdim,
                         const float* __restrict__ xx, float* __restrict__ pd) {
    __shared__ float As0[16][132], Ws0[16][68];
    __shared__ float As1[16][132], Ws1[16][68];
    int b = blockIdx.z;
    const float* Fb = F + (size_t)b*NN*fs;
    const float* xb = xx + b*NN;
    int tid = threadIdx.x;
    int tx = tid & 15, ty = tid >> 4;
    int n0 = blockIdx.x*128, m0 = blockIdx.y*64;
    int r0 = tid >> 2, kc = (tid & 3)*4;
    const float* Ar0 = Fb + (size_t)(n0 + r0)*fs + kc;
    const float* Ar1 = Fb + (size_t)(n0 + 64 + r0)*fs + kc;
    const float* Wr  = Fb + (size_t)(m0 + r0)*fs + kc;
    unsigned long long acc[4][4];
    #pragma unroll
    for (int i = 0; i < 4; i++)
        #pragma unroll
        for (int j = 0; j < 4; j++) acc[i][j] = 0ULL;

    GEMM_MAINLOOP(Ar0, Ar1, Wr, Kdim)

    float xm[4];
    #pragma unroll
    for (int j = 0; j < 4; j++) xm[j] = xb[m0 + tx*4 + j];
    float* prow = pd + (size_t)b*NN*NN;
    #pragma unroll
    for (int ip = 0; ip < 4; ip++) {
        float2 c0 = unpack2(acc[ip][0]);
        float2 c1 = unpack2(acc[ip][1]);
        float2 c2 = unpack2(acc[ip][2]);
        float2 c3 = unpack2(acc[ip][3]);
        int n = n0 + ty*8 + ip*2;
        float xn0 = xb[n], xn1 = xb[n+1];
        *(float4*)(prow + (size_t)n*NN + m0 + tx*4) =
            make_float4(2.f*c0.x - xn0 - xm[0], 2.f*c1.x - xn0 - xm[1],
                        2.f*c2.x - xn0 - xm[2], 2.f*c3.x - xn0 - xm[3]);
        *(float4*)(prow + (size_t)(n+1)*NN + m0 + tx*4) =
            make_float4(2.f*c0.y - xn1 - xm[0], 2.f*c1.y - xn1 - xm[1],
                        2.f*c2.y - xn1 - xm[2], 2.f*c3.y - xn1 - xm[3]);
    }
}

__global__ void k_topk_w(const float* __restrict__ pd, int* __restrict__ idx) {
    int warp = threadIdx.x >> 5;
    int lane = threadIdx.x & 31;
    int row = blockIdx.x*8 + warp;
    const float* prow = pd + (size_t)row*NN;
    float vals[32];
    #pragma unroll
    for (int j = 0; j < 32; j++) vals[j] = prow[j*32 + lane];
    warp_top20(vals, lane, idx + (size_t)row*KNN);
}

__global__ void k_wpack(const float* __restrict__ W, int C, int O, float* __restrict__ wc) {
    int i = blockIdx.x*blockDim.x + threadIdx.x;
    if (i >= 2*O*C) return;
    int o2 = i / C, c = i - o2*C;
    if (o2 < O) wc[i] = W[(size_t)o2*2*C + c];
    else {
        int o = o2 - O;
        wc[i] = W[(size_t)o*2*C + C + c] - W[(size_t)o*2*C + c];
    }
}

// W5 -> bf16 hi/lo split
__global__ void k_cvt_w5(const float* __restrict__ W5, __nv_bfloat16* __restrict__ wh,
                         __nv_bfloat16* __restrict__ wl) {
    int i = blockIdx.x*blockDim.x + threadIdx.x;
    if (i >= 1024*512) return;
    float w = W5[i];
    __nv_bfloat16 h = __float2bfloat16(w);
    wh[i] = h;
    wl[i] = __float2bfloat16(w - __bfloat162float(h));
}

__global__ void k_sgemm(const float* __restrict__ A, int lda,
                        const float* __restrict__ Bw, int ldb,
                        float* __restrict__ Cout, int Kdim, int O) {
    __shared__ float As[16][65], Ws[16][65];
    int tx = threadIdx.x, ty = threadIdx.y;
    int tid = ty*16 + tx;
    int m0 = blockIdx.x*64, o0 = blockIdx.y*64;
    float acc[4][4];
    #pragma unroll
    for (int i = 0; i < 4; i++)
        #pragma unroll
        for (int j = 0; j < 4; j++) acc[i][j] = 0.f;
    for (int k0 = 0; k0 < Kdim; k0 += 16) {
        #pragma unroll
        for (int r = 0; r < 4; r++) {
            int i  = tid + r*256;
            int kk = i & 15, mm = i >> 4;
            As[kk][mm] = (k0+kk < Kdim) ? A[(size_t)(m0+mm)*lda + k0+kk] : 0.f;
            Ws[kk][mm] = (k0+kk < Kdim) ? Bw[(size_t)(o0+mm)*ldb + k0+kk] : 0.f;
        }
        __syncthreads();
        #pragma unroll
        for (int kk = 0; kk < 16; kk++) {
            float a[4], bfr[4];
            #pragma unroll
            for (int i = 0; i < 4; i++) a[i] = As[kk][ty*4 + i];
            #pragma unroll
            for (int j = 0; j < 4; j++) bfr[j] = Ws[kk][tx*4 + j];
            #pragma unroll
            for (int i = 0; i < 4; i++)
                #pragma unroll
                for (int j = 0; j < 4; j++) acc[i][j] += a[i]*bfr[j];
        }
        __syncthreads();
    }
    #pragma unroll
    for (int i = 0; i < 4; i++)
        #pragma unroll
        for (int j = 0; j < 4; j++)
            Cout[(size_t)(m0 + ty*4 + i)*O + o0 + tx*4 + j] = acc[i][j];
}

__global__ void k_sgemm_f(const float* __restrict__ A, int lda,
                          const float* __restrict__ Bw, int ldb,
                          float* __restrict__ Cout, int ldc, int Kdim) {
    __shared__ float As0[16][132], Ws0[16][68];
    __shared__ float As1[16][132], Ws1[16][68];
    int tid = threadIdx.x;
    int tx = tid & 15, ty = tid >> 4;
    int m0 = blockIdx.x*128, o0 = blockIdx.y*64;
    int r0 = tid >> 2, kc = (tid & 3)*4;
    const float* Ar0 = A  + (size_t)(m0 + r0)*lda + kc;
    const float* Ar1 = A  + (size_t)(m0 + 64 + r0)*lda + kc;
    const float* Wr  = Bw + (size_t)(o0 + r0)*ldb + kc;
    unsigned long long acc[4][4];
    #pragma unroll
    for (int i = 0; i < 4; i++)
        #pragma unroll
        for (int j = 0; j < 4; j++) acc[i][j] = 0ULL;

    GEMM_MAINLOOP(Ar0, Ar1, Wr, Kdim)

    #pragma unroll
    for (int ip = 0; ip < 4; ip++) {
        float2 c0 = unpack2(acc[ip][0]);
        float2 c1 = unpack2(acc[ip][1]);
        float2 c2 = unpack2(acc[ip][2]);
        float2 c3 = unpack2(acc[ip][3]);
        int mrow = m0 + ty*8 + ip*2;
        *(float4*)(Cout + (size_t)mrow*ldc + o0 + tx*4) =
            make_float4(c0.x, c1.x, c2.x, c3.x);
        *(float4*)(Cout + (size_t)(mrow+1)*ldc + o0 + tx*4) =
            make_float4(c0.y, c1.y, c2.y, c3.y);
    }
}

// ---------------- layer-5 tensor-core GEMM via mma.sync (bf16 hi/lo split) ----
// h[m, o] = sum_k cat[m,k] * W5[o,k];  M=N=128 per block, K chunks of 64.
#define KC5 64
#define SA5 72                       // bf16 row stride in smem (+8 pad)
#define SM5_TILE (128*SA5)           // bf16 elements per tile
#define SM5_BYTES (4*SM5_TILE*2)     // Ah, Al, Bh, Bl

__global__ void __launch_bounds__(256, 1)
k_mma5(const float* __restrict__ cat, const __nv_bfloat16* __restrict__ w5h,
       const __nv_bfloat16* __restrict__ w5l, float* __restrict__ hout) {
    extern __shared__ __nv_bfloat16 sm[];
    __nv_bfloat16* Ah = sm;
    __nv_bfloat16* Al = sm + SM5_TILE;
    __nv_bfloat16* Bh = sm + 2*SM5_TILE;
    __nv_bfloat16* Bl = sm + 3*SM5_TILE;

    int tid = threadIdx.x;
    int warp = tid >> 5, lane = tid & 31;
    int g = lane >> 2, t = lane & 3;
    int m0 = blockIdx.x*128, o0 = blockIdx.y*128;
    int wm = (warp >> 2)*64;     // warp row offset (0 or 64)
    int wn = (warp & 3)*32;      // warp col offset (0,32,64,96)

    float acc[4][4][4];
    #pragma unroll
    for (int i = 0; i < 4; i++)
        #pragma unroll
        for (int j = 0; j < 4; j++)
            #pragma unroll
            for (int r = 0; r < 4; r++) acc[i][j][r] = 0.f;

    for (int kc = 0; kc < 512; kc += KC5) {
        // ---- load A (fp32 -> bf16 hi/lo) : 128 rows x 64 k ----
        #pragma unroll
        for (int it = 0; it < 8; it++) {
            int i = it*256 + tid;          // 0..2047
            int row = i >> 4, kq = (i & 15)*4;
            float4 v = *(const float4*)(cat + (size_t)(m0+row)*512 + kc + kq);
            __nv_bfloat16 h0 = __float2bfloat16(v.x), h1 = __float2bfloat16(v.y);
            __nv_bfloat16 h2 = __float2bfloat16(v.z), h3 = __float2bfloat16(v.w);
            __nv_bfloat16 l0 = __float2bfloat16(v.x - __bfloat162float(h0));
            __nv_bfloat16 l1 = __float2bfloat16(v.y - __bfloat162float(h1));
            __nv_bfloat16 l2 = __float2bfloat16(v.z - __bfloat162float(h2));
            __nv_bfloat16 l3 = __float2bfloat16(v.w - __bfloat162float(h3));
            uint2 hp, lp;
            hp.x = (uint32_t)__bfloat16_as_ushort(h1) << 16 | __bfloat16_as_ushort(h0);
            hp.y = (uint32_t)__bfloat16_as_ushort(h3) << 16 | __bfloat16_as_ushort(h2);
            lp.x = (uint32_t)__bfloat16_as_ushort(l1) << 16 | __bfloat16_as_ushort(l0);
            lp.y = (uint32_t)__bfloat16_as_ushort(l3) << 16 | __bfloat16_as_ushort(l2);
            *(uint2*)(Ah + row*SA5 + kq) = hp;
            *(uint2*)(Al + row*SA5 + kq) = lp;
        }
        // ---- load B (pre-split bf16) : 128 rows x 64 k ----
        #pragma unroll
        for (int it = 0; it < 4; it++) {
            int i = it*256 + tid;          // 0..1023
            int row = i >> 3, kq = (i & 7)*8;
            uint4 h = *(const uint4*)(w5h + (size_t)(o0+row)*512 + kc + kq);
            uint4 l = *(const uint4*)(w5l + (size_t)(o0+row)*512 + kc + kq);
            *(uint4*)(Bh + row*SA5 + kq) = h;
            *(uint4*)(Bl + row*SA5 + kq) = l;
        }
        __syncthreads();

        #pragma unroll
        for (int ks = 0; ks < KC5; ks += 16) {
            // A fragments for 4 m-tiles (hi and lo)
            uint32_t ah[4][4], al[4][4];
            #pragma unroll
            for (int mt = 0; mt < 4; mt++) {
                int r = wm + mt*16;
                ah[mt][0] = *(const uint32_t*)(Ah + (r+g  )*SA5 + ks + 2*t);
                ah[mt][1] = *(const uint32_t*)(Ah + (r+g+8)*SA5 + ks + 2*t);
                ah[mt][2] = *(const uint32_t*)(Ah + (r+g  )*SA5 + ks + 2*t + 8);
                ah[mt][3] = *(const uint32_t*)(Ah + (r+g+8)*SA5 + ks + 2*t + 8);
                al[mt][0] = *(const uint32_t*)(Al + (r+g  )*SA5 + ks + 2*t);
                al[mt][1] = *(const uint32_t*)(Al + (r+g+8)*SA5 + ks + 2*t);
                al[mt][2] = *(const uint32_t*)(Al + (r+g  )*SA5 + ks + 2*t + 8);
                al[mt][3] = *(const uint32_t*)(Al + (r+g+8)*SA5 + ks + 2*t + 8);
            }
            #pragma unroll
            for (int nt = 0; nt < 4; nt++) {
                int nr = wn + nt*8 + g;
                uint32_t bh[2], bl[2];
                bh[0] = *(const uint32_t*)(Bh + nr*SA5 + ks + 2*t);
                bh[1] = *(const uint32_t*)(Bh + nr*SA5 + ks + 2*t + 8);
                bl[0] = *(const uint32_t*)(Bl + nr*SA5 + ks + 2*t);
                bl[1] = *(const uint32_t*)(Bl + nr*SA5 + ks + 2*t + 8);
                #pragma unroll
                for (int mt = 0; mt < 4; mt++) {
                    mma16816(acc[mt][nt], ah[mt], bh);
                    mma16816(acc[mt][nt], ah[mt], bl);
                    mma16816(acc[mt][nt], al[mt], bh);
                }
            }
        }
        __syncthreads();
    }

    // epilogue: write h
    #pragma unroll
    for (int mt = 0; mt < 4; mt++) {
        int r0g = m0 + wm + mt*16 + g;
        #pragma unroll
        for (int nt = 0; nt < 4; nt++) {
            int col = o0 + wn + nt*8 + 2*t;
            *(float2*)(hout + (size_t)r0g*1024 + col)     = make_float2(acc[mt][nt][0], acc[mt][nt][1]);
            *(float2*)(hout + (size_t)(r0g+8)*1024 + col) = make_float2(acc[mt][nt][2], acc[mt][nt][3]);
        }
    }
}

__global__ void k_zero(float* a, float* b) { int t = threadIdx.x; a[t] = 0.f; b[t] = 0.f; }

__global__ void k_gather(const float* __restrict__ pq, const int* __restrict__ idx,
                         float* __restrict__ hmax,
                         float* __restrict__ sum, float* __restrict__ sumsq, int O) {
    int o  = threadIdx.x;
    int r0 = blockIdx.x*32;
    int b  = r0 >> 10;
    int ld = 2*O;
    __shared__ int sidx[32*KNN];
    for (int i = o; i < 32*KNN; i += blockDim.x) sidx[i] = idx[(size_t)r0*KNN + i];
    __syncthreads();
    const float* pb = pq + (size_t)b*NN*ld;
    float s = 0.f, s2 = 0.f;
    for (int n = 0; n < 32; n++) {
        int row = r0 + n;
        float cq = pq[(size_t)row*ld + O + o];
        float mx = -INFINITY;
        #pragma unroll
        for (int k = 0; k < KNN; k++) {
            float v = pb[(size_t)sidx[n*KNN + k]*ld + o];
            mx = fmaxf(mx, v);
            float h = v + cq;
            s += h; s2 += h*h;
        }
        hmax[(size_t)row*O + o] = mx + cq;
    }
    atomicAdd(&sum[o], s);
    atomicAdd(&sumsq[o], s2);
}

__global__ void k_bn(const float* __restrict__ hmax, const float* __restrict__ sum,
                     const float* __restrict__ sumsq,
                     const float* __restrict__ gamma, const float* __restrict__ beta,
                     float* __restrict__ out, int O, int os, float invCnt) {
    int e = blockIdx.x*blockDim.x + threadIdx.x;
    int row = e / O, o = e - row*O;
    float mean = sum[o]*invCnt;
    float var  = sumsq[o]*invCnt - mean*mean;
    float hn = (hmax[e] - mean)*rsqrtf(var + EPS)*gamma[o] + beta[o];
    out[(size_t)row*os + o] = hn >= 0.f ? hn : NEG_SLOPE*hn;
}

__global__ void k_reduce5(const float* __restrict__ h, float* __restrict__ bmax,
                          float* __restrict__ sum, float* __restrict__ sumsq) {
    int b = blockIdx.x;
    int o = blockIdx.y*256 + threadIdx.x;
    const float* hb = h + (size_t)b*NN*1024;
    float mx = -INFINITY, s = 0.f, s2 = 0.f;
    for (int n = 0; n < NN; n++) {
        float v = hb[(size_t)n*1024 + o];
        mx = fmaxf(mx, v); s += v; s2 += v*v;
    }
    bmax[b*1024 + o] = mx;
    atomicAdd(&sum[o], s);
    atomicAdd(&sumsq[o], s2);
}

__global__ void k_final(const float* __restrict__ bmax, const float* __restrict__ sum,
                        const float* __restrict__ sumsq,
                        const float* __restrict__ gamma, const float* __restrict__ beta,
                        float* __restrict__ out) {
    int e = blockIdx.x*blockDim.x + threadIdx.x;   // 32768
    int o = e & 1023;
    float invCnt = 1.f/32768.f;
    float mean = sum[o]*invCnt;
    float var  = sumsq[o]*invCnt - mean*mean;
    float hn = (bmax[e] - mean)*rsqrtf(var + EPS)*gamma[o] + beta[o];
    out[e] = hn >= 0.f ? hn : NEG_SLOPE*hn;
}

// ---------------- host driver ----------------

static void edge_layer_fast(const float* F, int fs, int C, int O,
                            const float* Wc, const float* ga, const float* be,
                            float* pd, int* idx, float* pq, float* hmax,
                            float* xx, float* sum, float* sumsq, float* catOut) {
    k_xx<<<RTOT/256, 256>>>(F, fs, C, xx);
    k_pair_f<<<dim3(8, 16, 32), 256>>>(F, fs, C, xx, pd);
    k_topk_w<<<RTOT/8, 256>>>(pd, idx);
    k_sgemm_f<<<dim3(RTOT/128, 2*O/64), 256>>>(F, fs, Wc, C, pq, 2*O, C);
    k_zero<<<1, 1024>>>(sum, sumsq);
    k_gather<<<RTOT/32, O>>>(pq, idx, hmax, sum, sumsq, O);
    k_bn<<<(RTOT*O)/256, 256>>>(hmax, sum, sumsq, ga, be, catOut, O, 512,
                                1.f/((float)RTOT*KNN));
}

extern "C" void kernel_launch(void* const* d_in, const int* in_sizes, int n_in,
                              void* d_out, int out_size) {
    const float* x = (const float*)d_in[0];
    const float* W[5]; const float* ga[5]; const float* be[5];
    for (int i = 0; i < 5; i++) {
        W[i]  = (const float*)d_in[1 + 3*i];
        ga[i] = (const float*)d_in[2 + 3*i];
        be[i] = (const float*)d_in[3 + 3*i];
    }

    float *pd, *pq, *hmax, *cat, *wc, *xx, *sum, *sumsq, *bmax;
    __nv_bfloat16 *w5h, *w5l;
    int *idx;
    cudaGetSymbolAddress((void**)&pd,    g_pd);
    cudaGetSymbolAddress((void**)&idx,   g_idx);
    cudaGetSymbolAddress((void**)&pq,    g_pq);
    cudaGetSymbolAddress((void**)&hmax,  g_hmax);
    cudaGetSymbolAddress((void**)&cat,   g_cat);
    cudaGetSymbolAddress((void**)&wc,    g_wc);
    cudaGetSymbolAddress((void**)&xx,    g_xx);
    cudaGetSymbolAddress((void**)&sum,   g_sum);
    cudaGetSymbolAddress((void**)&sumsq, g_sumsq);
    cudaGetSymbolAddress((void**)&bmax,  g_bmax);
    cudaGetSymbolAddress((void**)&w5h,   g_w5h);
    cudaGetSymbolAddress((void**)&w5l,   g_w5l);

    cudaFuncSetAttribute(k_mma5, cudaFuncAttributeMaxDynamicSharedMemorySize, SM5_BYTES);

    // packed weight slices + W5 split (only depend on W inputs)
    float* wc1 = wc;
    float* wc2 = wc1 + 512;
    float* wc3 = wc2 + 8192;
    float* wc4 = wc3 + 16384;
    k_wpack<<<(2*64*3   + 255)/256, 256>>>(W[0], 3,   64,  wc1);
    k_wpack<<<(2*64*64  + 255)/256, 256>>>(W[1], 64,  64,  wc2);
    k_wpack<<<(2*128*64 + 255)/256, 256>>>(W[2], 64,  128, wc3);
    k_wpack<<<(2*256*128+ 255)/256, 256>>>(W[3], 128, 256, wc4);
    k_cvt_w5<<<(1024*512 + 255)/256, 256>>>(W[4], w5h, w5l);

    // ---- layer 1 (C=3) ----
    k_knn3<<<dim3(128, 32), 256>>>(x, idx);
    k_sgemm<<<dim3(RTOT/64, 2), dim3(16,16)>>>(x, 3, wc1, 3, pq, 3, 128);
    k_zero<<<1, 1024>>>(sum, sumsq);
    k_gather<<<RTOT/32, 64>>>(pq, idx, hmax, sum, sumsq, 64);
    k_bn<<<(RTOT*64)/256, 256>>>(hmax, sum, sumsq, ga[0], be[0], cat + 0, 64, 512,
                                 1.f/((float)RTOT*KNN));

    // ---- layers 2-4 ----
    edge_layer_fast(cat+0,   512, 64,  64,  wc2, ga[1], be[1],
                    pd, idx, pq, hmax, xx, sum, sumsq, cat + 64);
    edge_layer_fast(cat+64,  512, 64,  128, wc3, ga[2], be[2],
                    pd, idx, pq, hmax, xx, sum, sumsq, cat + 128);
    edge_layer_fast(cat+128, 512, 128, 256, wc4, ga[3], be[3],
                    pd, idx, pq, hmax, xx, sum, sumsq, cat + 256);

    // ---- layer 5: mma.sync bf16-split GEMM -> h (g_pd), then reduce + BN ----
    k_mma5<<<dim3(RTOT/128, 1024/128), 256, SM5_BYTES>>>(cat, w5h, w5l, pd);
    k_zero<<<1, 1024>>>(sum, sumsq);
    k_reduce5<<<dim3(BB, 4), 256>>>(pd, bmax, sum, sumsq);
    k_final<<<RTOT/256, 256>>>(bmax, sum, sumsq, ga[4], be[4], (float*)d_out);
}

// round 8
// speedup vs baseline: 1.7843x; 1.0055x over previous
#include <cuda_runtime.h>
#include <cuda_bf16.h>
#include <math.h>
#include <stdint.h>

#define BB 32
#define NN 1024
#define KNN 20
#define RTOT (BB*NN)          // 32768 rows
#define NEG_SLOPE 0.2f
#define EPS 1e-5f

// ---------------- static scratch (allocation-free rule) ----------------
__device__ __align__(256) float g_pd[(size_t)BB*NN*NN];     // 128 MB
__device__ __align__(256) int   g_idx[(size_t)RTOT*KNN];
__device__ __align__(256) float g_pq[(size_t)RTOT*512];     // packed [p|q]
__device__ __align__(256) float g_hmax[(size_t)RTOT*256];
__device__ __align__(256) float g_cat[(size_t)RTOT*512];
__device__ __align__(256) float g_wc[1024*512];
__device__ __align__(256) float g_xx[RTOT];
__device__ __align__(256) float g_sum[1024];
__device__ __align__(256) float g_sumsq[1024];
__device__ __align__(256) float g_bmax[RTOT];
__device__ __align__(256) __nv_bfloat16 g_w5h[1024*512];
__device__ __align__(256) __nv_bfloat16 g_w5l[1024*512];

// ---------------- mma helpers ----------------
__device__ __forceinline__ void mma16816(float* c, const uint32_t* a, const uint32_t* b) {
    asm volatile("mma.sync.aligned.m16n8k16.row.col.f32.bf16.bf16.f32 "
        "{%0,%1,%2,%3}, {%4,%5,%6,%7}, {%8,%9}, {%0,%1,%2,%3};"
        : "+f"(c[0]), "+f"(c[1]), "+f"(c[2]), "+f"(c[3])
        : "r"(a[0]), "r"(a[1]), "r"(a[2]), "r"(a[3]), "r"(b[0]), "r"(b[1]));
}
__device__ __forceinline__ void mma1688(float* c, const uint32_t* a, const uint32_t* b) {
    asm volatile("mma.sync.aligned.m16n8k8.row.col.f32.tf32.tf32.f32 "
        "{%0,%1,%2,%3}, {%4,%5,%6,%7}, {%8,%9}, {%0,%1,%2,%3};"
        : "+f"(c[0]), "+f"(c[1]), "+f"(c[2]), "+f"(c[3])
        : "r"(a[0]), "r"(a[1]), "r"(a[2]), "r"(a[3]), "r"(b[0]), "r"(b[1]));
}
__device__ __forceinline__ void split_tf32(float v, uint32_t &hi, uint32_t &lo) {
    asm("cvt.rna.tf32.f32 %0, %1;" : "=r"(hi) : "f"(v));
    float r = v - __uint_as_float(hi);
    asm("cvt.rna.tf32.f32 %0, %1;" : "=r"(lo) : "f"(r));
}

// ---------------- TF32x3 tile engine: 128x128 C tile, 256 threads ----------------
// C[m, n] = sum_k A[m, k] * B[n, k]  (both row-major, k-contiguous)
#define ST32 36
#define SMT32_FLOATS (4*128*ST32)
#define SMT32_BYTES  (SMT32_FLOATS*4)

__device__ __forceinline__ void t32_load_tile(const float* __restrict__ P, int ldp,
                                              int kc, float* sh, float* sl, int tid) {
    #pragma unroll
    for (int it = 0; it < 4; it++) {
        int i = it*256 + tid;
        int row = i >> 3, kq = (i & 7)*4;
        float4 v = *(const float4*)(P + (size_t)row*ldp + kc + kq);
        uint32_t h0,l0,h1,l1,h2,l2,h3,l3;
        split_tf32(v.x, h0, l0); split_tf32(v.y, h1, l1);
        split_tf32(v.z, h2, l2); split_tf32(v.w, h3, l3);
        uint32_t* ph = (uint32_t*)sh + row*ST32 + kq;
        uint32_t* pl = (uint32_t*)sl + row*ST32 + kq;
        ph[0]=h0; ph[1]=h1; ph[2]=h2; ph[3]=h3;
        pl[0]=l0; pl[1]=l1; pl[2]=l2; pl[3]=l3;
    }
}

__device__ __forceinline__ void t32_tile(const float* __restrict__ A, int lda,
                                         const float* __restrict__ Bw, int ldb, int Kdim,
                                         float* sAh, float* sAl, float* sBh, float* sBl,
                                         int tid, float (&acc)[4][4][4]) {
    int warp = tid >> 5, lane = tid & 31;
    int g = lane >> 2, t = lane & 3;
    int wm = (warp >> 2)*64, wn = (warp & 3)*32;
    for (int kc = 0; kc < Kdim; kc += 32) {
        t32_load_tile(A,  lda, kc, sAh, sAl, tid);
        t32_load_tile(Bw, ldb, kc, sBh, sBl, tid);
        __syncthreads();
        #pragma unroll
        for (int ks = 0; ks < 32; ks += 8) {
            uint32_t ah[4][4], al[4][4];
            #pragma unroll
            for (int mt = 0; mt < 4; mt++) {
                const uint32_t* bh = (uint32_t*)sAh + (wm + mt*16)*ST32 + ks;
                const uint32_t* bl = (uint32_t*)sAl + (wm + mt*16)*ST32 + ks;
                ah[mt][0] = bh[g*ST32 + t];       ah[mt][1] = bh[(g+8)*ST32 + t];
                ah[mt][2] = bh[g*ST32 + t + 4];   ah[mt][3] = bh[(g+8)*ST32 + t + 4];
                al[mt][0] = bl[g*ST32 + t];       al[mt][1] = bl[(g+8)*ST32 + t];
                al[mt][2] = bl[g*ST32 + t + 4];   al[mt][3] = bl[(g+8)*ST32 + t + 4];
            }
            #pragma unroll
            for (int nt = 0; nt < 4; nt++) {
                const uint32_t* ph = (uint32_t*)sBh + (wn + nt*8 + g)*ST32 + ks;
                const uint32_t* pl = (uint32_t*)sBl + (wn + nt*8 + g)*ST32 + ks;
                uint32_t bh[2] = {ph[t], ph[t+4]};
                uint32_t bl[2] = {pl[t], pl[t+4]};
                #pragma unroll
                for (int mt = 0; mt < 4; mt++) {
                    mma1688(acc[mt][nt], ah[mt], bh);
                    mma1688(acc[mt][nt], ah[mt], bl);
                    mma1688(acc[mt][nt], al[mt], bh);
                }
            }
        }
        __syncthreads();
    }
}

// pairwise distances via TF32x3: pd[b,n,m] = 2<F_n,F_m> - xx_n - xx_m
__global__ void __launch_bounds__(256)
k_pair_t32(const float* __restrict__ F, int fs, int Kdim,
           const float* __restrict__ xx, float* __restrict__ pd) {
    extern __shared__ float sm32[];
    float* sAh = sm32;
    float* sAl = sm32 + 128*ST32;
    float* sBh = sm32 + 2*128*ST32;
    float* sBl = sm32 + 3*128*ST32;
    int b = blockIdx.z;
    const float* Fb = F + (size_t)b*NN*fs;
    const float* xb = xx + b*NN;
    int n0 = blockIdx.x*128, m0 = blockIdx.y*128;
    int tid = threadIdx.x;
    float acc[4][4][4];
    #pragma unroll
    for (int i = 0; i < 4; i++)
        #pragma unroll
        for (int j = 0; j < 4; j++)
            #pragma unroll
            for (int r = 0; r < 4; r++) acc[i][j][r] = 0.f;

    t32_tile(Fb + (size_t)n0*fs, fs, Fb + (size_t)m0*fs, fs, Kdim,
             sAh, sAl, sBh, sBl, tid, acc);

    int warp = tid >> 5, lane = tid & 31;
    int g = lane >> 2, t = lane & 3;
    int wm = (warp >> 2)*64, wn = (warp & 3)*32;
    float* pb = pd + (size_t)b*NN*NN;
    #pragma unroll
    for (int mt = 0; mt < 4; mt++) {
        int n = n0 + wm + mt*16 + g;
        float xn0 = xb[n], xn1 = xb[n+8];
        #pragma unroll
        for (int nt = 0; nt < 4; nt++) {
            int col = m0 + wn + nt*8 + 2*t;
            float xm0 = xb[col], xm1 = xb[col+1];
            *(float2*)(pb + (size_t)n*NN + col) =
                make_float2(2.f*acc[mt][nt][0] - xn0 - xm0, 2.f*acc[mt][nt][1] - xn0 - xm1);
            *(float2*)(pb + (size_t)(n+8)*NN + col) =
                make_float2(2.f*acc[mt][nt][2] - xn1 - xm0, 2.f*acc[mt][nt][3] - xn1 - xm1);
        }
    }
}

// p/q GEMM via TF32x3: Cout[m, n] = sum_k A[m,k]*Bw[n,k]
__global__ void __launch_bounds__(256)
k_pq_t32(const float* __restrict__ A, int lda, const float* __restrict__ Bw, int ldb,
         float* __restrict__ Cout, int ldc, int Kdim) {
    extern __shared__ float sm32[];
    float* sAh = sm32;
    float* sAl = sm32 + 128*ST32;
    float* sBh = sm32 + 2*128*ST32;
    float* sBl = sm32 + 3*128*ST32;
    int m0 = blockIdx.x*128, o0 = blockIdx.y*128;
    int tid = threadIdx.x;
    float acc[4][4][4];
    #pragma unroll
    for (int i = 0; i < 4; i++)
        #pragma unroll
        for (int j = 0; j < 4; j++)
            #pragma unroll
            for (int r = 0; r < 4; r++) acc[i][j][r] = 0.f;

    t32_tile(A + (size_t)m0*lda, lda, Bw + (size_t)o0*ldb, ldb, Kdim,
             sAh, sAl, sBh, sBl, tid, acc);

    int warp = tid >> 5, lane = tid & 31;
    int g = lane >> 2, t = lane & 3;
    int wm = (warp >> 2)*64, wn = (warp & 3)*32;
    #pragma unroll
    for (int mt = 0; mt < 4; mt++) {
        int r = m0 + wm + mt*16 + g;
        #pragma unroll
        for (int nt = 0; nt < 4; nt++) {
            int col = o0 + wn + nt*8 + 2*t;
            *(float2*)(Cout + (size_t)r*ldc + col)     = make_float2(acc[mt][nt][0], acc[mt][nt][1]);
            *(float2*)(Cout + (size_t)(r+8)*ldc + col) = make_float2(acc[mt][nt][2], acc[mt][nt][3]);
        }
    }
}

// ---------------- warp top-20 over 32x32 register tile ----------------
__device__ __forceinline__ void warp_top20(float (&vals)[32], int lane, int* orow) {
    unsigned rm = 0;
    float bv = vals[0]; int bslot = 0;
    #pragma unroll
    for (int j = 1; j < 32; j++) { float v = vals[j]; if (v > bv) { bv = v; bslot = j; } }
    for (int it = 0; it < KNN; it++) {
        float cv = bv;
        int ci = (bslot >= 0) ? (bslot*32 + lane) : 0x7fffffff;
        if (bslot < 0) cv = -INFINITY;
        #pragma unroll
        for (int s = 16; s > 0; s >>= 1) {
            float ov = __shfl_xor_sync(0xffffffffu, cv, s);
            int   oi = __shfl_xor_sync(0xffffffffu, ci, s);
            if (ov > cv || (ov == cv && oi < ci)) { cv = ov; ci = oi; }
        }
        if (lane == 0) orow[it] = ci;
        if ((ci & 31) == lane) {
            rm |= 1u << (ci >> 5);
            bv = -INFINITY; bslot = -1;
            #pragma unroll
            for (int j = 0; j < 32; j++) {
                if (!((rm >> j) & 1u)) {
                    float v = vals[j];
                    if (v > bv) { bv = v; bslot = j; }
                }
            }
        }
    }
}

// ---------------- kernels ----------------

__global__ void k_xx(const float* __restrict__ F, int fs, int C, float* __restrict__ xx) {
    int r = blockIdx.x*blockDim.x + threadIdx.x;
    if (r >= RTOT) return;
    const float* f = F + (size_t)r*fs;
    float s = 0.f;
    for (int c = 0; c < C; c++) { float v = f[c]; s += v*v; }
    xx[r] = s;
}

__global__ void k_knn3(const float* __restrict__ x, int* __restrict__ idx) {
    __shared__ float sx[NN], sy[NN], sz[NN];
    int b = blockIdx.y;
    const float* xb = x + (size_t)b*NN*3;
    int tid = threadIdx.x;
    for (int i = tid; i < NN; i += 256) {
        sx[i] = xb[i*3+0]; sy[i] = xb[i*3+1]; sz[i] = xb[i*3+2];
    }
    __syncthreads();
    int warp = tid >> 5, lane = tid & 31;
    int n = blockIdx.x*8 + warp;
    float xnx = sx[n], xny = sy[n], xnz = sz[n];
    float xxn = xnx*xnx; xxn += xny*xny; xxn += xnz*xnz;
    float vals[32];
    #pragma unroll
    for (int j = 0; j < 32; j++) {
        int m = j*32 + lane;
        float mx = sx[m], my = sy[m], mz = sz[m];
        float inner = xnx*mx; inner += xny*my; inner += xnz*mz;
        float xxm = mx*mx; xxm += my*my; xxm += mz*mz;
        vals[j] = 2.f*inner - xxn - xxm;
    }
    warp_top20(vals, lane, idx + (size_t)(b*NN + n)*KNN);
}

__global__ void k_topk_w(const float* __restrict__ pd, int* __restrict__ idx) {
    int warp = threadIdx.x >> 5;
    int lane = threadIdx.x & 31;
    int row = blockIdx.x*8 + warp;
    const float* prow = pd + (size_t)row*NN;
    float vals[32];
    #pragma unroll
    for (int j = 0; j < 32; j++) vals[j] = prow[j*32 + lane];
    warp_top20(vals, lane, idx + (size_t)row*KNN);
}

__global__ void k_wpack(const float* __restrict__ W, int C, int O, float* __restrict__ wc) {
    int i = blockIdx.x*blockDim.x + threadIdx.x;
    if (i >= 2*O*C) return;
    int o2 = i / C, c = i - o2*C;
    if (o2 < O) wc[i] = W[(size_t)o2*2*C + c];
    else {
        int o = o2 - O;
        wc[i] = W[(size_t)o*2*C + C + c] - W[(size_t)o*2*C + c];
    }
}

// W5 -> bf16 hi/lo split
__global__ void k_cvt_w5(const float* __restrict__ W5, __nv_bfloat16* __restrict__ wh,
                         __nv_bfloat16* __restrict__ wl) {
    int i = blockIdx.x*blockDim.x + threadIdx.x;
    if (i >= 1024*512) return;
    float w = W5[i];
    __nv_bfloat16 h = __float2bfloat16(w);
    wh[i] = h;
    wl[i] = __float2bfloat16(w - __bfloat162float(h));
}

__global__ void k_sgemm(const float* __restrict__ A, int lda,
                        const float* __restrict__ Bw, int ldb,
                        float* __restrict__ Cout, int Kdim, int O) {
    __shared__ float As[16][65], Ws[16][65];
    int tx = threadIdx.x, ty = threadIdx.y;
    int tid = ty*16 + tx;
    int m0 = blockIdx.x*64, o0 = blockIdx.y*64;
    float acc[4][4];
    #pragma unroll
    for (int i = 0; i < 4; i++)
        #pragma unroll
        for (int j = 0; j < 4; j++) acc[i][j] = 0.f;
    for (int k0 = 0; k0 < Kdim; k0 += 16) {
        #pragma unroll
        for (int r = 0; r < 4; r++) {
            int i  = tid + r*256;
            int kk = i & 15, mm = i >> 4;
            As[kk][mm] = (k0+kk < Kdim) ? A[(size_t)(m0+mm)*lda + k0+kk] : 0.f;
            Ws[kk][mm] = (k0+kk < Kdim) ? Bw[(size_t)(o0+mm)*ldb + k0+kk] : 0.f;
        }
        __syncthreads();
        #pragma unroll
        for (int kk = 0; kk < 16; kk++) {
            float a[4], bfr[4];
            #pragma unroll
            for (int i = 0; i < 4; i++) a[i] = As[kk][ty*4 + i];
            #pragma unroll
            for (int j = 0; j < 4; j++) bfr[j] = Ws[kk][tx*4 + j];
            #pragma unroll
            for (int i = 0; i < 4; i++)
                #pragma unroll
                for (int j = 0; j < 4; j++) acc[i][j] += a[i]*bfr[j];
        }
        __syncthreads();
    }
    #pragma unroll
    for (int i = 0; i < 4; i++)
        #pragma unroll
        for (int j = 0; j < 4; j++)
            Cout[(size_t)(m0 + ty*4 + i)*O + o0 + tx*4 + j] = acc[i][j];
}

// ---------------- layer-5 tensor-core GEMM via mma.sync (bf16 hi/lo split) ----
#define KC5 64
#define SA5 72
#define SM5_TILE (128*SA5)
#define SM5_BYTES (4*SM5_TILE*2)

__global__ void __launch_bounds__(256, 1)
k_mma5(const float* __restrict__ cat, const __nv_bfloat16* __restrict__ w5h,
       const __nv_bfloat16* __restrict__ w5l, float* __restrict__ hout) {
    extern __shared__ __nv_bfloat16 sm[];
    __nv_bfloat16* Ah = sm;
    __nv_bfloat16* Al = sm + SM5_TILE;
    __nv_bfloat16* Bh = sm + 2*SM5_TILE;
    __nv_bfloat16* Bl = sm + 3*SM5_TILE;

    int tid = threadIdx.x;
    int warp = tid >> 5, lane = tid & 31;
    int g = lane >> 2, t = lane & 3;
    int m0 = blockIdx.x*128, o0 = blockIdx.y*128;
    int wm = (warp >> 2)*64;
    int wn = (warp & 3)*32;

    float acc[4][4][4];
    #pragma unroll
    for (int i = 0; i < 4; i++)
        #pragma unroll
        for (int j = 0; j < 4; j++)
            #pragma unroll
            for (int r = 0; r < 4; r++) acc[i][j][r] = 0.f;

    for (int kc = 0; kc < 512; kc += KC5) {
        #pragma unroll
        for (int it = 0; it < 8; it++) {
            int i = it*256 + tid;
            int row = i >> 4, kq = (i & 15)*4;
            float4 v = *(const float4*)(cat + (size_t)(m0+row)*512 + kc + kq);
            __nv_bfloat16 h0 = __float2bfloat16(v.x), h1 = __float2bfloat16(v.y);
            __nv_bfloat16 h2 = __float2bfloat16(v.z), h3 = __float2bfloat16(v.w);
            __nv_bfloat16 l0 = __float2bfloat16(v.x - __bfloat162float(h0));
            __nv_bfloat16 l1 = __float2bfloat16(v.y - __bfloat162float(h1));
            __nv_bfloat16 l2 = __float2bfloat16(v.z - __bfloat162float(h2));
            __nv_bfloat16 l3 = __float2bfloat16(v.w - __bfloat162float(h3));
            uint2 hp, lp;
            hp.x = (uint32_t)__bfloat16_as_ushort(h1) << 16 | __bfloat16_as_ushort(h0);
            hp.y = (uint32_t)__bfloat16_as_ushort(h3) << 16 | __bfloat16_as_ushort(h2);
            lp.x = (uint32_t)__bfloat16_as_ushort(l1) << 16 | __bfloat16_as_ushort(l0);
            lp.y = (uint32_t)__bfloat16_as_ushort(l3) << 16 | __bfloat16_as_ushort(l2);
            *(uint2*)(Ah + row*SA5 + kq) = hp;
            *(uint2*)(Al + row*SA5 + kq) = lp;
        }
        #pragma unroll
        for (int it = 0; it < 4; it++) {
            int i = it*256 + tid;
            int row = i >> 3, kq = (i & 7)*8;
            uint4 h = *(const uint4*)(w5h + (size_t)(o0+row)*512 + kc + kq);
            uint4 l = *(const uint4*)(w5l + (size_t)(o0+row)*512 + kc + kq);
            *(uint4*)(Bh + row*SA5 + kq) = h;
            *(uint4*)(Bl + row*SA5 + kq) = l;
        }
        __syncthreads();

        #pragma unroll
        for (int ks = 0; ks < KC5; ks += 16) {
            uint32_t ah[4][4], al[4][4];
            #pragma unroll
            for (int mt = 0; mt < 4; mt++) {
                int r = wm + mt*16;
                ah[mt][0] = *(const uint32_t*)(Ah + (r+g  )*SA5 + ks + 2*t);
                ah[mt][1] = *(const uint32_t*)(Ah + (r+g+8)*SA5 + ks + 2*t);
                ah[mt][2] = *(const uint32_t*)(Ah + (r+g  )*SA5 + ks + 2*t + 8);
                ah[mt][3] = *(const uint32_t*)(Ah + (r+g+8)*SA5 + ks + 2*t + 8);
                al[mt][0] = *(const uint32_t*)(Al + (r+g  )*SA5 + ks + 2*t);
                al[mt][1] = *(const uint32_t*)(Al + (r+g+8)*SA5 + ks + 2*t);
                al[mt][2] = *(const uint32_t*)(Al + (r+g  )*SA5 + ks + 2*t + 8);
                al[mt][3] = *(const uint32_t*)(Al + (r+g+8)*SA5 + ks + 2*t + 8);
            }
            #pragma unroll
            for (int nt = 0; nt < 4; nt++) {
                int nr = wn + nt*8 + g;
                uint32_t bh[2], bl[2];
                bh[0] = *(const uint32_t*)(Bh + nr*SA5 + ks + 2*t);
                bh[1] = *(const uint32_t*)(Bh + nr*SA5 + ks + 2*t + 8);
                bl[0] = *(const uint32_t*)(Bl + nr*SA5 + ks + 2*t);
                bl[1] = *(const uint32_t*)(Bl + nr*SA5 + ks + 2*t + 8);
                #pragma unroll
                for (int mt = 0; mt < 4; mt++) {
                    mma16816(acc[mt][nt], ah[mt], bh);
                    mma16816(acc[mt][nt], ah[mt], bl);
                    mma16816(acc[mt][nt], al[mt], bh);
                }
            }
        }
        __syncthreads();
    }

    #pragma unroll
    for (int mt = 0; mt < 4; mt++) {
        int r0g = m0 + wm + mt*16 + g;
        #pragma unroll
        for (int nt = 0; nt < 4; nt++) {
            int col = o0 + wn + nt*8 + 2*t;
            *(float2*)(hout + (size_t)r0g*1024 + col)     = make_float2(acc[mt][nt][0], acc[mt][nt][1]);
            *(float2*)(hout + (size_t)(r0g+8)*1024 + col) = make_float2(acc[mt][nt][2], acc[mt][nt][3]);
        }
    }
}

__global__ void k_zero(float* a, float* b) { int t = threadIdx.x; a[t] = 0.f; b[t] = 0.f; }

__global__ void k_gather(const float* __restrict__ pq, const int* __restrict__ idx,
                         float* __restrict__ hmax,
                         float* __restrict__ sum, float* __restrict__ sumsq, int O) {
    int o  = threadIdx.x;
    int r0 = blockIdx.x*32;
    int b  = r0 >> 10;
    int ld = 2*O;
    __shared__ int sidx[32*KNN];
    for (int i = o; i < 32*KNN; i += blockDim.x) sidx[i] = idx[(size_t)r0*KNN + i];
    __syncthreads();
    const float* pb = pq + (size_t)b*NN*ld;
    float s = 0.f, s2 = 0.f;
    for (int n = 0; n < 32; n++) {
        int row = r0 + n;
        float cq = pq[(size_t)row*ld + O + o];
        float mx = -INFINITY;
        #pragma unroll
        for (int k = 0; k < KNN; k++) {
            float v = pb[(size_t)sidx[n*KNN + k]*ld + o];
            mx = fmaxf(mx, v);
            float h = v + cq;
            s += h; s2 += h*h;
        }
        hmax[(size_t)row*O + o] = mx + cq;
    }
    atomicAdd(&sum[o], s);
    atomicAdd(&sumsq[o], s2);
}

__global__ void k_bn(const float* __restrict__ hmax, const float* __restrict__ sum,
                     const float* __restrict__ sumsq,
                     const float* __restrict__ gamma, const float* __restrict__ beta,
                     float* __restrict__ out, int O, int os, float invCnt) {
    int e = blockIdx.x*blockDim.x + threadIdx.x;
    int row = e / O, o = e - row*O;
    float mean = sum[o]*invCnt;
    float var  = sumsq[o]*invCnt - mean*mean;
    float hn = (hmax[e] - mean)*rsqrtf(var + EPS)*gamma[o] + beta[o];
    out[(size_t)row*os + o] = hn >= 0.f ? hn : NEG_SLOPE*hn;
}

__global__ void k_reduce5(const float* __restrict__ h, float* __restrict__ bmax,
                          float* __restrict__ sum, float* __restrict__ sumsq) {
    int b = blockIdx.x;
    int o = blockIdx.y*256 + threadIdx.x;
    const float* hb = h + (size_t)b*NN*1024;
    float mx = -INFINITY, s = 0.f, s2 = 0.f;
    for (int n = 0; n < NN; n++) {
        float v = hb[(size_t)n*1024 + o];
        mx = fmaxf(mx, v); s += v; s2 += v*v;
    }
    bmax[b*1024 + o] = mx;
    atomicAdd(&sum[o], s);
    atomicAdd(&sumsq[o], s2);
}

__global__ void k_final(const float* __restrict__ bmax, const float* __restrict__ sum,
                        const float* __restrict__ sumsq,
                        const float* __restrict__ gamma, const float* __restrict__ beta,
                        float* __restrict__ out) {
    int e = blockIdx.x*blockDim.x + threadIdx.x;   // 32768
    int o = e & 1023;
    float invCnt = 1.f/32768.f;
    float mean = sum[o]*invCnt;
    float var  = sumsq[o]*invCnt - mean*mean;
    float hn = (bmax[e] - mean)*rsqrtf(var + EPS)*gamma[o] + beta[o];
    out[e] = hn >= 0.f ? hn : NEG_SLOPE*hn;
}

// ---------------- host driver ----------------

static void edge_layer_fast(const float* F, int fs, int C, int O,
                            const float* Wc, const float* ga, const float* be,
                            float* pd, int* idx, float* pq, float* hmax,
                            float* xx, float* sum, float* sumsq, float* catOut) {
    k_xx<<<RTOT/256, 256>>>(F, fs, C, xx);
    k_pair_t32<<<dim3(8, 8, 32), 256, SMT32_BYTES>>>(F, fs, C, xx, pd);
    k_topk_w<<<RTOT/8, 256>>>(pd, idx);
    k_pq_t32<<<dim3(RTOT/128, 2*O/128), 256, SMT32_BYTES>>>(F, fs, Wc, C, pq, 2*O, C);
    k_zero<<<1, 1024>>>(sum, sumsq);
    k_gather<<<RTOT/32, O>>>(pq, idx, hmax, sum, sumsq, O);
    k_bn<<<(RTOT*O)/256, 256>>>(hmax, sum, sumsq, ga, be, catOut, O, 512,
                                1.f/((float)RTOT*KNN));
}

extern "C" void kernel_launch(void* const* d_in, const int* in_sizes, int n_in,
                              void* d_out, int out_size) {
    const float* x = (const float*)d_in[0];
    const float* W[5]; const float* ga[5]; const float* be[5];
    for (int i = 0; i < 5; i++) {
        W[i]  = (const float*)d_in[1 + 3*i];
        ga[i] = (const float*)d_in[2 + 3*i];
        be[i] = (const float*)d_in[3 + 3*i];
    }

    float *pd, *pq, *hmax, *cat, *wc, *xx, *sum, *sumsq, *bmax;
    __nv_bfloat16 *w5h, *w5l;
    int *idx;
    cudaGetSymbolAddress((void**)&pd,    g_pd);
    cudaGetSymbolAddress((void**)&idx,   g_idx);
    cudaGetSymbolAddress((void**)&pq,    g_pq);
    cudaGetSymbolAddress((void**)&hmax,  g_hmax);
    cudaGetSymbolAddress((void**)&cat,   g_cat);
    cudaGetSymbolAddress((void**)&wc,    g_wc);
    cudaGetSymbolAddress((void**)&xx,    g_xx);
    cudaGetSymbolAddress((void**)&sum,   g_sum);
    cudaGetSymbolAddress((void**)&sumsq, g_sumsq);
    cudaGetSymbolAddress((void**)&bmax,  g_bmax);
    cudaGetSymbolAddress((void**)&w5h,   g_w5h);
    cudaGetSymbolAddress((void**)&w5l,   g_w5l);

    cudaFuncSetAttribute(k_mma5, cudaFuncAttributeMaxDynamicSharedMemorySize, SM5_BYTES);
    cudaFuncSetAttribute(k_pair_t32, cudaFuncAttributeMaxDynamicSharedMemorySize, SMT32_BYTES);
    cudaFuncSetAttribute(k_pq_t32, cudaFuncAttributeMaxDynamicSharedMemorySize, SMT32_BYTES);

    // packed weight slices + W5 split (only depend on W inputs)
    float* wc1 = wc;
    float* wc2 = wc1 + 512;
    float* wc3 = wc2 + 8192;
    float* wc4 = wc3 + 16384;
    k_wpack<<<(2*64*3   + 255)/256, 256>>>(W[0], 3,   64,  wc1);
    k_wpack<<<(2*64*64  + 255)/256, 256>>>(W[1], 64,  64,  wc2);
    k_wpack<<<(2*128*64 + 255)/256, 256>>>(W[2], 64,  128, wc3);
    k_wpack<<<(2*256*128+ 255)/256, 256>>>(W[3], 128, 256, wc4);
    k_cvt_w5<<<(1024*512 + 255)/256, 256>>>(W[4], w5h, w5l);

    // ---- layer 1 (C=3) ----
    k_knn3<<<dim3(128, 32), 256>>>(x, idx);
    k_sgemm<<<dim3(RTOT/64, 2), dim3(16,16)>>>(x, 3, wc1, 3, pq, 3, 128);
    k_zero<<<1, 1024>>>(sum, sumsq);
    k_gather<<<RTOT/32, 64>>>(pq, idx, hmax, sum, sumsq, 64);
    k_bn<<<(RTOT*64)/256, 256>>>(hmax, sum, sumsq, ga[0], be[0], cat + 0, 64, 512,
                                 1.f/((float)RTOT*KNN));

    // ---- layers 2-4 (TF32x3 tensor path) ----
    edge_layer_fast(cat+0,   512, 64,  64,  wc2, ga[1], be[1],
                    pd, idx, pq, hmax, xx, sum, sumsq, cat + 64);
    edge_layer_fast(cat+64,  512, 64,  128, wc3, ga[2], be[2],
                    pd, idx, pq, hmax, xx, sum, sumsq, cat + 128);
    edge_layer_fast(cat+128, 512, 128, 256, wc4, ga[3], be[3],
                    pd, idx, pq, hmax, xx, sum, sumsq, cat + 256);

    // ---- layer 5: mma.sync bf16-split GEMM -> h (g_pd), then reduce + BN ----
    k_mma5<<<dim3(RTOT/128, 1024/128), 256, SM5_BYTES>>>(cat, w5h, w5l, pd);
    k_zero<<<1, 1024>>>(sum, sumsq);
    k_reduce5<<<dim3(BB, 4), 256>>>(pd, bmax, sum, sumsq);
    k_final<<<RTOT/256, 256>>>(bmax, sum, sumsq, ga[4], be[4], (float*)d_out);
}

// round 9
// speedup vs baseline: 1.8290x; 1.0250x over previous
#include <cuda_runtime.h>
#include <cuda_bf16.h>
#include <math.h>
#include <stdint.h>

#define BB 32
#define NN 1024
#define KNN 20
#define RTOT (BB*NN)          // 32768 rows
#define NEG_SLOPE 0.2f
#define EPS 1e-5f

// ---------------- static scratch (allocation-free rule) ----------------
__device__ __align__(256) float g_pd[(size_t)BB*NN*NN];     // 128 MB
__device__ __align__(256) int   g_idx[(size_t)RTOT*KNN];
__device__ __align__(256) float g_pq[(size_t)RTOT*512];     // packed [p|q]
__device__ __align__(256) float g_hmax[(size_t)RTOT*256];
__device__ __align__(256) float g_wc[1024];                 // layer-1 packed W (fp32)
__device__ __align__(256) float g_wch[131072];              // tf32-hi packed W, layers 2-4
__device__ __align__(256) float g_wcl[131072];              // tf32-lo
__device__ __align__(256) float g_fh[(size_t)RTOT*128];     // tf32-hi features (next layer)
__device__ __align__(256) float g_fl[(size_t)RTOT*128];
__device__ __align__(256) __nv_bfloat16 g_c5h[(size_t)RTOT*512];  // bf16-hi cat
__device__ __align__(256) __nv_bfloat16 g_c5l[(size_t)RTOT*512];  // bf16-lo cat
__device__ __align__(256) float g_xx[RTOT];
__device__ __align__(256) float g_sum[1024];
__device__ __align__(256) float g_sumsq[1024];
__device__ __align__(256) float g_bmax[RTOT];
__device__ __align__(256) __nv_bfloat16 g_w5h[1024*512];
__device__ __align__(256) __nv_bfloat16 g_w5l[1024*512];

// ---------------- mma helpers ----------------
__device__ __forceinline__ void mma16816(float* c, const uint32_t* a, const uint32_t* b) {
    asm volatile("mma.sync.aligned.m16n8k16.row.col.f32.bf16.bf16.f32 "
        "{%0,%1,%2,%3}, {%4,%5,%6,%7}, {%8,%9}, {%0,%1,%2,%3};"
        : "+f"(c[0]), "+f"(c[1]), "+f"(c[2]), "+f"(c[3])
        : "r"(a[0]), "r"(a[1]), "r"(a[2]), "r"(a[3]), "r"(b[0]), "r"(b[1]));
}
__device__ __forceinline__ void mma1688(float* c, const uint32_t* a, const uint32_t* b) {
    asm volatile("mma.sync.aligned.m16n8k8.row.col.f32.tf32.tf32.f32 "
        "{%0,%1,%2,%3}, {%4,%5,%6,%7}, {%8,%9}, {%0,%1,%2,%3};"
        : "+f"(c[0]), "+f"(c[1]), "+f"(c[2]), "+f"(c[3])
        : "r"(a[0]), "r"(a[1]), "r"(a[2]), "r"(a[3]), "r"(b[0]), "r"(b[1]));
}
__device__ __forceinline__ void split_tf32(float v, uint32_t &hi, uint32_t &lo) {
    asm("cvt.rna.tf32.f32 %0, %1;" : "=r"(hi) : "f"(v));
    float r = v - __uint_as_float(hi);
    asm("cvt.rna.tf32.f32 %0, %1;" : "=r"(lo) : "f"(r));
}

// ---------------- TF32x3 tile engine: 128x128 C tile, 256 threads ----------------
// Operands are PRE-SPLIT tf32 hi/lo float arrays (k-contiguous rows).
#define ST32 36
#define SMT32_FLOATS (4*128*ST32)
#define SMT32_BYTES  (SMT32_FLOATS*4)

__device__ __forceinline__ void t32_load_pre(const float* __restrict__ Ph,
                                             const float* __restrict__ Pl, int ldp,
                                             int kc, float* sh, float* sl, int tid) {
    #pragma unroll
    for (int it = 0; it < 4; it++) {
        int i = it*256 + tid;
        int row = i >> 3, kq = (i & 7)*4;
        uint4 h = *(const uint4*)(Ph + (size_t)row*ldp + kc + kq);
        uint4 l = *(const uint4*)(Pl + (size_t)row*ldp + kc + kq);
        *(uint4*)((uint32_t*)sh + row*ST32 + kq) = h;
        *(uint4*)((uint32_t*)sl + row*ST32 + kq) = l;
    }
}

__device__ __forceinline__ void t32_tile(const float* __restrict__ Ah_g, const float* __restrict__ Al_g, int lda,
                                         const float* __restrict__ Bh_g, const float* __restrict__ Bl_g, int ldb,
                                         int Kdim,
                                         float* sAh, float* sAl, float* sBh, float* sBl,
                                         int tid, float (&acc)[4][4][4]) {
    int warp = tid >> 5, lane = tid & 31;
    int g = lane >> 2, t = lane & 3;
    int wm = (warp >> 2)*64, wn = (warp & 3)*32;
    for (int kc = 0; kc < Kdim; kc += 32) {
        t32_load_pre(Ah_g, Al_g, lda, kc, sAh, sAl, tid);
        t32_load_pre(Bh_g, Bl_g, ldb, kc, sBh, sBl, tid);
        __syncthreads();
        #pragma unroll
        for (int ks = 0; ks < 32; ks += 8) {
            uint32_t ah[4][4], al[4][4];
            #pragma unroll
            for (int mt = 0; mt < 4; mt++) {
                const uint32_t* bh = (uint32_t*)sAh + (wm + mt*16)*ST32 + ks;
                const uint32_t* bl = (uint32_t*)sAl + (wm + mt*16)*ST32 + ks;
                ah[mt][0] = bh[g*ST32 + t];       ah[mt][1] = bh[(g+8)*ST32 + t];
                ah[mt][2] = bh[g*ST32 + t + 4];   ah[mt][3] = bh[(g+8)*ST32 + t + 4];
                al[mt][0] = bl[g*ST32 + t];       al[mt][1] = bl[(g+8)*ST32 + t];
                al[mt][2] = bl[g*ST32 + t + 4];   al[mt][3] = bl[(g+8)*ST32 + t + 4];
            }
            #pragma unroll
            for (int nt = 0; nt < 4; nt++) {
                const uint32_t* ph = (uint32_t*)sBh + (wn + nt*8 + g)*ST32 + ks;
                const uint32_t* pl = (uint32_t*)sBl + (wn + nt*8 + g)*ST32 + ks;
                uint32_t bh[2] = {ph[t], ph[t+4]};
                uint32_t bl[2] = {pl[t], pl[t+4]};
                #pragma unroll
                for (int mt = 0; mt < 4; mt++) {
                    mma1688(acc[mt][nt], ah[mt], bh);
                    mma1688(acc[mt][nt], ah[mt], bl);
                    mma1688(acc[mt][nt], al[mt], bh);
                }
            }
        }
        __syncthreads();
    }
}

// pairwise distances: pd[b,n,m] = 2<F_n,F_m> - xx_n - xx_m (F pre-split tf32)
__global__ void __launch_bounds__(256)
k_pair_t32(const float* __restrict__ fh, const float* __restrict__ fl, int Kdim,
           const float* __restrict__ xx, float* __restrict__ pd) {
    extern __shared__ float sm32[];
    float* sAh = sm32;
    float* sAl = sm32 + 128*ST32;
    float* sBh = sm32 + 2*128*ST32;
    float* sBl = sm32 + 3*128*ST32;
    int b = blockIdx.z;
    const float* Fh = fh + (size_t)b*NN*Kdim;
    const float* Fl = fl + (size_t)b*NN*Kdim;
    const float* xb = xx + b*NN;
    int n0 = blockIdx.x*128, m0 = blockIdx.y*128;
    int tid = threadIdx.x;
    float acc[4][4][4];
    #pragma unroll
    for (int i = 0; i < 4; i++)
        #pragma unroll
        for (int j = 0; j < 4; j++)
            #pragma unroll
            for (int r = 0; r < 4; r++) acc[i][j][r] = 0.f;

    t32_tile(Fh + (size_t)n0*Kdim, Fl + (size_t)n0*Kdim, Kdim,
             Fh + (size_t)m0*Kdim, Fl + (size_t)m0*Kdim, Kdim, Kdim,
             sAh, sAl, sBh, sBl, tid, acc);

    int warp = tid >> 5, lane = tid & 31;
    int g = lane >> 2, t = lane & 3;
    int wm = (warp >> 2)*64, wn = (warp & 3)*32;
    float* pb = pd + (size_t)b*NN*NN;
    #pragma unroll
    for (int mt = 0; mt < 4; mt++) {
        int n = n0 + wm + mt*16 + g;
        float xn0 = xb[n], xn1 = xb[n+8];
        #pragma unroll
        for (int nt = 0; nt < 4; nt++) {
            int col = m0 + wn + nt*8 + 2*t;
            float xm0 = xb[col], xm1 = xb[col+1];
            *(float2*)(pb + (size_t)n*NN + col) =
                make_float2(2.f*acc[mt][nt][0] - xn0 - xm0, 2.f*acc[mt][nt][1] - xn0 - xm1);
            *(float2*)(pb + (size_t)(n+8)*NN + col) =
                make_float2(2.f*acc[mt][nt][2] - xn1 - xm0, 2.f*acc[mt][nt][3] - xn1 - xm1);
        }
    }
}

// p/q GEMM: Cout[m, n] = sum_k F[m,k]*Wc[n,k]  (pre-split operands)
__global__ void __launch_bounds__(256)
k_pq_t32(const float* __restrict__ fh, const float* __restrict__ fl, int lda,
         const float* __restrict__ wh, const float* __restrict__ wl, int ldb,
         float* __restrict__ Cout, int ldc, int Kdim) {
    extern __shared__ float sm32[];
    float* sAh = sm32;
    float* sAl = sm32 + 128*ST32;
    float* sBh = sm32 + 2*128*ST32;
    float* sBl = sm32 + 3*128*ST32;
    int m0 = blockIdx.x*128, o0 = blockIdx.y*128;
    int tid = threadIdx.x;
    float acc[4][4][4];
    #pragma unroll
    for (int i = 0; i < 4; i++)
        #pragma unroll
        for (int j = 0; j < 4; j++)
            #pragma unroll
            for (int r = 0; r < 4; r++) acc[i][j][r] = 0.f;

    t32_tile(fh + (size_t)m0*lda, fl + (size_t)m0*lda, lda,
             wh + (size_t)o0*ldb, wl + (size_t)o0*ldb, ldb, Kdim,
             sAh, sAl, sBh, sBl, tid, acc);

    int warp = tid >> 5, lane = tid & 31;
    int g = lane >> 2, t = lane & 3;
    int wm = (warp >> 2)*64, wn = (warp & 3)*32;
    #pragma unroll
    for (int mt = 0; mt < 4; mt++) {
        int r = m0 + wm + mt*16 + g;
        #pragma unroll
        for (int nt = 0; nt < 4; nt++) {
            int col = o0 + wn + nt*8 + 2*t;
            *(float2*)(Cout + (size_t)r*ldc + col)     = make_float2(acc[mt][nt][0], acc[mt][nt][1]);
            *(float2*)(Cout + (size_t)(r+8)*ldc + col) = make_float2(acc[mt][nt][2], acc[mt][nt][3]);
        }
    }
}

// ---------------- warp top-20 over 32x32 register tile ----------------
__device__ __forceinline__ void warp_top20(float (&vals)[32], int lane, int* orow) {
    unsigned rm = 0;
    float bv = vals[0]; int bslot = 0;
    #pragma unroll
    for (int j = 1; j < 32; j++) { float v = vals[j]; if (v > bv) { bv = v; bslot = j; } }
    for (int it = 0; it < KNN; it++) {
        float cv = bv;
        int ci = (bslot >= 0) ? (bslot*32 + lane) : 0x7fffffff;
        if (bslot < 0) cv = -INFINITY;
        #pragma unroll
        for (int s = 16; s > 0; s >>= 1) {
            float ov = __shfl_xor_sync(0xffffffffu, cv, s);
            int   oi = __shfl_xor_sync(0xffffffffu, ci, s);
            if (ov > cv || (ov == cv && oi < ci)) { cv = ov; ci = oi; }
        }
        if (lane == 0) orow[it] = ci;
        if ((ci & 31) == lane) {
            rm |= 1u << (ci >> 5);
            bv = -INFINITY; bslot = -1;
            #pragma unroll
            for (int j = 0; j < 32; j++) {
                if (!((rm >> j) & 1u)) {
                    float v = vals[j];
                    if (v > bv) { bv = v; bslot = j; }
                }
            }
        }
    }
}

// ---------------- kernels ----------------

// layer-1 KNN (C=3) + zero stats fold
__global__ void k_knn3(const float* __restrict__ x, int* __restrict__ idx,
                       float* __restrict__ sum, float* __restrict__ sumsq) {
    __shared__ float sx[NN], sy[NN], sz[NN];
    int b = blockIdx.y;
    const float* xb = x + (size_t)b*NN*3;
    int tid = threadIdx.x;
    if (blockIdx.x == 0 && b == 0) {
        for (int i = tid; i < 1024; i += 256) { sum[i] = 0.f; sumsq[i] = 0.f; }
    }
    for (int i = tid; i < NN; i += 256) {
        sx[i] = xb[i*3+0]; sy[i] = xb[i*3+1]; sz[i] = xb[i*3+2];
    }
    __syncthreads();
    int warp = tid >> 5, lane = tid & 31;
    int n = blockIdx.x*8 + warp;
    float xnx = sx[n], xny = sy[n], xnz = sz[n];
    float xxn = xnx*xnx; xxn += xny*xny; xxn += xnz*xnz;
    float vals[32];
    #pragma unroll
    for (int j = 0; j < 32; j++) {
        int m = j*32 + lane;
        float mx = sx[m], my = sy[m], mz = sz[m];
        float inner = xnx*mx; inner += xny*my; inner += xnz*mz;
        float xxm = mx*mx; xxm += my*my; xxm += mz*mz;
        vals[j] = 2.f*inner - xxn - xxm;
    }
    warp_top20(vals, lane, idx + (size_t)(b*NN + n)*KNN);
}

// top-20 from pd + zero stats fold
__global__ void k_topk_w(const float* __restrict__ pd, int* __restrict__ idx,
                         float* __restrict__ sum, float* __restrict__ sumsq) {
    int tid = threadIdx.x;
    if (blockIdx.x == 0) {
        for (int i = tid; i < 1024; i += 256) { sum[i] = 0.f; sumsq[i] = 0.f; }
    }
    int warp = tid >> 5;
    int lane = tid & 31;
    int row = blockIdx.x*8 + warp;
    const float* prow = pd + (size_t)row*NN;
    float vals[32];
    #pragma unroll
    for (int j = 0; j < 32; j++) vals[j] = prow[j*32 + lane];
    warp_top20(vals, lane, idx + (size_t)row*KNN);
}

// layer-1 packed weights (fp32)
__global__ void k_wpack(const float* __restrict__ W, int C, int O, float* __restrict__ wc) {
    int i = blockIdx.x*blockDim.x + threadIdx.x;
    if (i >= 2*O*C) return;
    int o2 = i / C, c = i - o2*C;
    if (o2 < O) wc[i] = W[(size_t)o2*2*C + c];
    else {
        int o = o2 - O;
        wc[i] = W[(size_t)o*2*C + C + c] - W[(size_t)o*2*C + c];
    }
}

// layers 2-4 packed weights, tf32 pre-split
__global__ void k_wpack_t32(const float* __restrict__ W, int C, int O,
                            float* __restrict__ wh, float* __restrict__ wl) {
    int i = blockIdx.x*blockDim.x + threadIdx.x;
    if (i >= 2*O*C) return;
    int o2 = i / C, c = i - o2*C;
    float v;
    if (o2 < O) v = W[(size_t)o2*2*C + c];
    else {
        int o = o2 - O;
        v = W[(size_t)o*2*C + C + c] - W[(size_t)o*2*C + c];
    }
    uint32_t hi, lo;
    split_tf32(v, hi, lo);
    wh[i] = __uint_as_float(hi);
    wl[i] = __uint_as_float(lo);
}

// W5 -> bf16 hi/lo split
__global__ void k_cvt_w5(const float* __restrict__ W5, __nv_bfloat16* __restrict__ wh,
                         __nv_bfloat16* __restrict__ wl) {
    int i = blockIdx.x*blockDim.x + threadIdx.x;
    if (i >= 1024*512) return;
    float w = W5[i];
    __nv_bfloat16 h = __float2bfloat16(w);
    wh[i] = h;
    wl[i] = __float2bfloat16(w - __bfloat162float(h));
}

// layer-1 tiny GEMM (K=3)
__global__ void k_sgemm(const float* __restrict__ A, int lda,
                        const float* __restrict__ Bw, int ldb,
                        float* __restrict__ Cout, int Kdim, int O) {
    __shared__ float As[16][65], Ws[16][65];
    int tx = threadIdx.x, ty = threadIdx.y;
    int tid = ty*16 + tx;
    int m0 = blockIdx.x*64, o0 = blockIdx.y*64;
    float acc[4][4];
    #pragma unroll
    for (int i = 0; i < 4; i++)
        #pragma unroll
        for (int j = 0; j < 4; j++) acc[i][j] = 0.f;
    for (int k0 = 0; k0 < Kdim; k0 += 16) {
        #pragma unroll
        for (int r = 0; r < 4; r++) {
            int i  = tid + r*256;
            int kk = i & 15, mm = i >> 4;
            As[kk][mm] = (k0+kk < Kdim) ? A[(size_t)(m0+mm)*lda + k0+kk] : 0.f;
            Ws[kk][mm] = (k0+kk < Kdim) ? Bw[(size_t)(o0+mm)*ldb + k0+kk] : 0.f;
        }
        __syncthreads();
        #pragma unroll
        for (int kk = 0; kk < 16; kk++) {
            float a[4], bfr[4];
            #pragma unroll
            for (int i = 0; i < 4; i++) a[i] = As[kk][ty*4 + i];
            #pragma unroll
            for (int j = 0; j < 4; j++) bfr[j] = Ws[kk][tx*4 + j];
            #pragma unroll
            for (int i = 0; i < 4; i++)
                #pragma unroll
                for (int j = 0; j < 4; j++) acc[i][j] += a[i]*bfr[j];
        }
        __syncthreads();
    }
    #pragma unroll
    for (int i = 0; i < 4; i++)
        #pragma unroll
        for (int j = 0; j < 4; j++)
            Cout[(size_t)(m0 + ty*4 + i)*O + o0 + tx*4 + j] = acc[i][j];
}

// ---------------- layer-5 tensor-core GEMM (bf16 hi/lo, PRE-SPLIT operands) ----
#define KC5 64
#define SA5 72
#define SM5_TILE (128*SA5)
#define SM5_BYTES (4*SM5_TILE*2)

__global__ void __launch_bounds__(256, 1)
k_mma5(const __nv_bfloat16* __restrict__ c5h, const __nv_bfloat16* __restrict__ c5l,
       const __nv_bfloat16* __restrict__ w5h, const __nv_bfloat16* __restrict__ w5l,
       float* __restrict__ hout, float* __restrict__ sum, float* __restrict__ sumsq) {
    extern __shared__ __nv_bfloat16 sm[];
    __nv_bfloat16* Ah = sm;
    __nv_bfloat16* Al = sm + SM5_TILE;
    __nv_bfloat16* Bh = sm + 2*SM5_TILE;
    __nv_bfloat16* Bl = sm + 3*SM5_TILE;

    int tid = threadIdx.x;
    if (blockIdx.x == 0 && blockIdx.y == 0) {
        for (int i = tid; i < 1024; i += 256) { sum[i] = 0.f; sumsq[i] = 0.f; }
    }
    int warp = tid >> 5, lane = tid & 31;
    int g = lane >> 2, t = lane & 3;
    int m0 = blockIdx.x*128, o0 = blockIdx.y*128;
    int wm = (warp >> 2)*64;
    int wn = (warp & 3)*32;

    float acc[4][4][4];
    #pragma unroll
    for (int i = 0; i < 4; i++)
        #pragma unroll
        for (int j = 0; j < 4; j++)
            #pragma unroll
            for (int r = 0; r < 4; r++) acc[i][j][r] = 0.f;

    for (int kc = 0; kc < 512; kc += KC5) {
        #pragma unroll
        for (int it = 0; it < 4; it++) {
            int i = it*256 + tid;
            int row = i >> 3, kq = (i & 7)*8;
            uint4 h = *(const uint4*)(c5h + (size_t)(m0+row)*512 + kc + kq);
            uint4 l = *(const uint4*)(c5l + (size_t)(m0+row)*512 + kc + kq);
            *(uint4*)(Ah + row*SA5 + kq) = h;
            *(uint4*)(Al + row*SA5 + kq) = l;
        }
        #pragma unroll
        for (int it = 0; it < 4; it++) {
            int i = it*256 + tid;
            int row = i >> 3, kq = (i & 7)*8;
            uint4 h = *(const uint4*)(w5h + (size_t)(o0+row)*512 + kc + kq);
            uint4 l = *(const uint4*)(w5l + (size_t)(o0+row)*512 + kc + kq);
            *(uint4*)(Bh + row*SA5 + kq) = h;
            *(uint4*)(Bl + row*SA5 + kq) = l;
        }
        __syncthreads();

        #pragma unroll
        for (int ks = 0; ks < KC5; ks += 16) {
            uint32_t ah[4][4], al[4][4];
            #pragma unroll
            for (int mt = 0; mt < 4; mt++) {
                int r = wm + mt*16;
                ah[mt][0] = *(const uint32_t*)(Ah + (r+g  )*SA5 + ks + 2*t);
                ah[mt][1] = *(const uint32_t*)(Ah + (r+g+8)*SA5 + ks + 2*t);
                ah[mt][2] = *(const uint32_t*)(Ah + (r+g  )*SA5 + ks + 2*t + 8);
                ah[mt][3] = *(const uint32_t*)(Ah + (r+g+8)*SA5 + ks + 2*t + 8);
                al[mt][0] = *(const uint32_t*)(Al + (r+g  )*SA5 + ks + 2*t);
                al[mt][1] = *(const uint32_t*)(Al + (r+g+8)*SA5 + ks + 2*t);
                al[mt][2] = *(const uint32_t*)(Al + (r+g  )*SA5 + ks + 2*t + 8);
                al[mt][3] = *(const uint32_t*)(Al + (r+g+8)*SA5 + ks + 2*t + 8);
            }
            #pragma unroll
            for (int nt = 0; nt < 4; nt++) {
                int nr = wn + nt*8 + g;
                uint32_t bh[2], bl[2];
                bh[0] = *(const uint32_t*)(Bh + nr*SA5 + ks + 2*t);
                bh[1] = *(const uint32_t*)(Bh + nr*SA5 + ks + 2*t + 8);
                bl[0] = *(const uint32_t*)(Bl + nr*SA5 + ks + 2*t);
                bl[1] = *(const uint32_t*)(Bl + nr*SA5 + ks + 2*t + 8);
                #pragma unroll
                for (int mt = 0; mt < 4; mt++) {
                    mma16816(acc[mt][nt], ah[mt], bh);
                    mma16816(acc[mt][nt], ah[mt], bl);
                    mma16816(acc[mt][nt], al[mt], bh);
                }
            }
        }
        __syncthreads();
    }

    #pragma unroll
    for (int mt = 0; mt < 4; mt++) {
        int r0g = m0 + wm + mt*16 + g;
        #pragma unroll
        for (int nt = 0; nt < 4; nt++) {
            int col = o0 + wn + nt*8 + 2*t;
            *(float2*)(hout + (size_t)r0g*1024 + col)     = make_float2(acc[mt][nt][0], acc[mt][nt][1]);
            *(float2*)(hout + (size_t)(r0g+8)*1024 + col) = make_float2(acc[mt][nt][2], acc[mt][nt][3]);
        }
    }
}

__global__ void k_gather(const float* __restrict__ pq, const int* __restrict__ idx,
                         float* __restrict__ hmax,
                         float* __restrict__ sum, float* __restrict__ sumsq, int O) {
    int o  = threadIdx.x;
    int r0 = blockIdx.x*32;
    int b  = r0 >> 10;
    int ld = 2*O;
    __shared__ int sidx[32*KNN];
    for (int i = o; i < 32*KNN; i += blockDim.x) sidx[i] = idx[(size_t)r0*KNN + i];
    __syncthreads();
    const float* pb = pq + (size_t)b*NN*ld;
    float s = 0.f, s2 = 0.f;
    for (int n = 0; n < 32; n++) {
        int row = r0 + n;
        float cq = pq[(size_t)row*ld + O + o];
        float mx = -INFINITY;
        #pragma unroll
        for (int k = 0; k < KNN; k++) {
            float v = pb[(size_t)sidx[n*KNN + k]*ld + o];
            mx = fmaxf(mx, v);
            float h = v + cq;
            s += h; s2 += h*h;
        }
        hmax[(size_t)row*O + o] = mx + cq;
    }
    atomicAdd(&sum[o], s);
    atomicAdd(&sumsq[o], s2);
}

// warp-per-row BN + lrelu; emits bf16 split into cat arrays (+ optional tf32 split + xx)
__global__ void k_bn_f(const float* __restrict__ hmax, const float* __restrict__ sum,
                       const float* __restrict__ sumsq,
                       const float* __restrict__ gamma, const float* __restrict__ beta,
                       __nv_bfloat16* __restrict__ c5h, __nv_bfloat16* __restrict__ c5l, int coff,
                       float* __restrict__ fh, float* __restrict__ fl, float* __restrict__ xx,
                       int O, float invCnt, int wantNext) {
    int warp = threadIdx.x >> 5, lane = threadIdx.x & 31;
    int row = blockIdx.x*8 + warp;
    float s2 = 0.f;
    for (int o = lane; o < O; o += 32) {
        float mean = sum[o]*invCnt;
        float var  = sumsq[o]*invCnt - mean*mean;
        float hn = (hmax[(size_t)row*O + o] - mean)*rsqrtf(var + EPS)*gamma[o] + beta[o];
        hn = hn >= 0.f ? hn : NEG_SLOPE*hn;
        __nv_bfloat16 h = __float2bfloat16(hn);
        c5h[(size_t)row*512 + coff + o] = h;
        c5l[(size_t)row*512 + coff + o] = __float2bfloat16(hn - __bfloat162float(h));
        if (wantNext) {
            uint32_t thi, tlo;
            split_tf32(hn, thi, tlo);
            fh[(size_t)row*O + o] = __uint_as_float(thi);
            fl[(size_t)row*O + o] = __uint_as_float(tlo);
            s2 += hn*hn;
        }
    }
    if (wantNext) {
        #pragma unroll
        for (int s = 16; s > 0; s >>= 1) s2 += __shfl_xor_sync(0xffffffffu, s2, s);
        if (lane == 0) xx[row] = s2;
    }
}

__global__ void k_reduce5(const float* __restrict__ h, float* __restrict__ bmax,
                          float* __restrict__ sum, float* __restrict__ sumsq) {
    int b = blockIdx.x;
    int o = blockIdx.y*256 + threadIdx.x;
    const float* hb = h + (size_t)b*NN*1024;
    float mx = -INFINITY, s = 0.f, s2 = 0.f;
    for (int n = 0; n < NN; n++) {
        float v = hb[(size_t)n*1024 + o];
        mx = fmaxf(mx, v); s += v; s2 += v*v;
    }
    bmax[b*1024 + o] = mx;
    atomicAdd(&sum[o], s);
    atomicAdd(&sumsq[o], s2);
}

__global__ void k_final(const float* __restrict__ bmax, const float* __restrict__ sum,
                        const float* __restrict__ sumsq,
                        const float* __restrict__ gamma, const float* __restrict__ beta,
                        float* __restrict__ out) {
    int e = blockIdx.x*blockDim.x + threadIdx.x;   // 32768
    int o = e & 1023;
    float invCnt = 1.f/32768.f;
    float mean = sum[o]*invCnt;
    float var  = sumsq[o]*invCnt - mean*mean;
    float hn = (bmax[e] - mean)*rsqrtf(var + EPS)*gamma[o] + beta[o];
    out[e] = hn >= 0.f ? hn : NEG_SLOPE*hn;
}

// ---------------- host driver ----------------

extern "C" void kernel_launch(void* const* d_in, const int* in_sizes, int n_in,
                              void* d_out, int out_size) {
    const float* x = (const float*)d_in[0];
    const float* W[5]; const float* ga[5]; const float* be[5];
    for (int i = 0; i < 5; i++) {
        W[i]  = (const float*)d_in[1 + 3*i];
        ga[i] = (const float*)d_in[2 + 3*i];
        be[i] = (const float*)d_in[3 + 3*i];
    }

    float *pd, *pq, *hmax, *wc, *wch, *wcl, *fh, *fl, *xx, *sum, *sumsq, *bmax;
    __nv_bfloat16 *c5h, *c5l, *w5h, *w5l;
    int *idx;
    cudaGetSymbolAddress((void**)&pd,    g_pd);
    cudaGetSymbolAddress((void**)&idx,   g_idx);
    cudaGetSymbolAddress((void**)&pq,    g_pq);
    cudaGetSymbolAddress((void**)&hmax,  g_hmax);
    cudaGetSymbolAddress((void**)&wc,    g_wc);
    cudaGetSymbolAddress((void**)&wch,   g_wch);
    cudaGetSymbolAddress((void**)&wcl,   g_wcl);
    cudaGetSymbolAddress((void**)&fh,    g_fh);
    cudaGetSymbolAddress((void**)&fl,    g_fl);
    cudaGetSymbolAddress((void**)&xx,    g_xx);
    cudaGetSymbolAddress((void**)&sum,   g_sum);
    cudaGetSymbolAddress((void**)&sumsq, g_sumsq);
    cudaGetSymbolAddress((void**)&bmax,  g_bmax);
    cudaGetSymbolAddress((void**)&c5h,   g_c5h);
    cudaGetSymbolAddress((void**)&c5l,   g_c5l);
    cudaGetSymbolAddress((void**)&w5h,   g_w5h);
    cudaGetSymbolAddress((void**)&w5l,   g_w5l);

    cudaFuncSetAttribute(k_mma5, cudaFuncAttributeMaxDynamicSharedMemorySize, SM5_BYTES);
    cudaFuncSetAttribute(k_pair_t32, cudaFuncAttributeMaxDynamicSharedMemorySize, SMT32_BYTES);
    cudaFuncSetAttribute(k_pq_t32, cudaFuncAttributeMaxDynamicSharedMemorySize, SMT32_BYTES);

    // packed-weight offsets in wch/wcl (tf32 split): L2 @0 (8192), L3 @8192 (16384), L4 @24576 (65536)
    float* wch2 = wch;           float* wcl2 = wcl;
    float* wch3 = wch + 8192;    float* wcl3 = wcl + 8192;
    float* wch4 = wch + 24576;   float* wcl4 = wcl + 24576;

    const float invKN = 1.f/((float)RTOT*KNN);

    // ---- layer 1 (C=3) — ordered so 6th launch overall = k_pair_t32 (profiled) ----
    k_wpack<<<(2*64*3 + 255)/256, 256>>>(W[0], 3, 64, wc);                 // 1
    k_knn3<<<dim3(128, 32), 256>>>(x, idx, sum, sumsq);                    // 2 (+zero)
    k_sgemm<<<dim3(RTOT/64, 2), dim3(16,16)>>>(x, 3, wc, 3, pq, 3, 128);   // 3
    k_gather<<<RTOT/32, 64>>>(pq, idx, hmax, sum, sumsq, 64);              // 4
    k_bn_f<<<RTOT/8, 256>>>(hmax, sum, sumsq, ga[0], be[0],
                            c5h, c5l, 0, fh, fl, xx, 64, invKN, 1);        // 5

    // ---- layer 2 ----
    k_pair_t32<<<dim3(8, 8, 32), 256, SMT32_BYTES>>>(fh, fl, 64, xx, pd);  // 6 <- profiled
    k_wpack_t32<<<(2*64*64  + 255)/256, 256>>>(W[1], 64,  64,  wch2, wcl2);
    k_wpack_t32<<<(2*128*64 + 255)/256, 256>>>(W[2], 64,  128, wch3, wcl3);
    k_wpack_t32<<<(2*256*128+ 255)/256, 256>>>(W[3], 128, 256, wch4, wcl4);
    k_cvt_w5<<<(1024*512 + 255)/256, 256>>>(W[4], w5h, w5l);
    k_topk_w<<<RTOT/8, 256>>>(pd, idx, sum, sumsq);
    k_pq_t32<<<dim3(RTOT/128, 1), 256, SMT32_BYTES>>>(fh, fl, 64, wch2, wcl2, 64, pq, 128, 64);
    k_gather<<<RTOT/32, 64>>>(pq, idx, hmax, sum, sumsq, 64);
    k_bn_f<<<RTOT/8, 256>>>(hmax, sum, sumsq, ga[1], be[1],
                            c5h, c5l, 64, fh, fl, xx, 64, invKN, 1);

    // ---- layer 3 ----
    k_pair_t32<<<dim3(8, 8, 32), 256, SMT32_BYTES>>>(fh, fl, 64, xx, pd);
    k_topk_w<<<RTOT/8, 256>>>(pd, idx, sum, sumsq);
    k_pq_t32<<<dim3(RTOT/128, 2), 256, SMT32_BYTES>>>(fh, fl, 64, wch3, wcl3, 64, pq, 256, 64);
    k_gather<<<RTOT/32, 128>>>(pq, idx, hmax, sum, sumsq, 128);
    k_bn_f<<<RTOT/8, 256>>>(hmax, sum, sumsq, ga[2], be[2],
                            c5h, c5l, 128, fh, fl, xx, 128, invKN, 1);

    // ---- layer 4 ----
    k_pair_t32<<<dim3(8, 8, 32), 256, SMT32_BYTES>>>(fh, fl, 128, xx, pd);
    k_topk_w<<<RTOT/8, 256>>>(pd, idx, sum, sumsq);
    k_pq_t32<<<dim3(RTOT/128, 4), 256, SMT32_BYTES>>>(fh, fl, 128, wch4, wcl4, 128, pq, 512, 128);
    k_gather<<<RTOT/32, 256>>>(pq, idx, hmax, sum, sumsq, 256);
    k_bn_f<<<RTOT/8, 256>>>(hmax, sum, sumsq, ga[3], be[3],
                            c5h, c5l, 256, fh, fl, xx, 256, invKN, 0);

    // ---- layer 5 ----
    k_mma5<<<dim3(RTOT/128, 1024/128), 256, SM5_BYTES>>>(c5h, c5l, w5h, w5l, pd, sum, sumsq);
    k_reduce5<<<dim3(BB, 4), 256>>>(pd, bmax, sum, sumsq);
    k_final<<<RTOT/256, 256>>>(bmax, sum, sumsq, ga[4], be[4], (float*)d_out);
}

// round 10
// speedup vs baseline: 1.8993x; 1.0384x over previous
#include <cuda_runtime.h>
#include <cuda_bf16.h>
#include <math.h>
#include <stdint.h>

#define BB 32
#define NN 1024
#define KNN 20
#define RTOT (BB*NN)          // 32768 rows
#define NEG_SLOPE 0.2f
#define EPS 1e-5f

// ---------------- static scratch (allocation-free rule) ----------------
__device__ __align__(256) float g_pd[(size_t)BB*NN*NN];     // 128 MB
__device__ __align__(256) int   g_idx[(size_t)RTOT*KNN];
__device__ __align__(256) float g_pq[(size_t)RTOT*512];     // packed [p|q]
__device__ __align__(256) float g_hmax[(size_t)RTOT*256];
__device__ __align__(256) float g_wc[1024];                 // layer-1 packed W (fp32)
__device__ __align__(256) float g_wch[131072];              // tf32-hi packed W, layers 2-4
__device__ __align__(256) float g_wcl[131072];              // tf32-lo
__device__ __align__(256) float g_fh[(size_t)RTOT*128];     // tf32-hi features (next layer)
__device__ __align__(256) float g_fl[(size_t)RTOT*128];
__device__ __align__(256) __nv_bfloat16 g_c5h[(size_t)RTOT*512];  // bf16-hi cat
__device__ __align__(256) __nv_bfloat16 g_c5l[(size_t)RTOT*512];  // bf16-lo cat
__device__ __align__(256) float g_xx[RTOT];
__device__ __align__(256) float g_sum[1024];
__device__ __align__(256) float g_sumsq[1024];
__device__ __align__(256) float g_redp[BB*8*1024];          // layer-5 partial maxes
__device__ __align__(256) __nv_bfloat16 g_w5h[1024*512];
__device__ __align__(256) __nv_bfloat16 g_w5l[1024*512];

// ---------------- mma helpers ----------------
__device__ __forceinline__ void mma16816(float* c, const uint32_t* a, const uint32_t* b) {
    asm volatile("mma.sync.aligned.m16n8k16.row.col.f32.bf16.bf16.f32 "
        "{%0,%1,%2,%3}, {%4,%5,%6,%7}, {%8,%9}, {%0,%1,%2,%3};"
        : "+f"(c[0]), "+f"(c[1]), "+f"(c[2]), "+f"(c[3])
        : "r"(a[0]), "r"(a[1]), "r"(a[2]), "r"(a[3]), "r"(b[0]), "r"(b[1]));
}
__device__ __forceinline__ void mma1688(float* c, const uint32_t* a, const uint32_t* b) {
    asm volatile("mma.sync.aligned.m16n8k8.row.col.f32.tf32.tf32.f32 "
        "{%0,%1,%2,%3}, {%4,%5,%6,%7}, {%8,%9}, {%0,%1,%2,%3};"
        : "+f"(c[0]), "+f"(c[1]), "+f"(c[2]), "+f"(c[3])
        : "r"(a[0]), "r"(a[1]), "r"(a[2]), "r"(a[3]), "r"(b[0]), "r"(b[1]));
}
__device__ __forceinline__ void split_tf32(float v, uint32_t &hi, uint32_t &lo) {
    asm("cvt.rna.tf32.f32 %0, %1;" : "=r"(hi) : "f"(v));
    float r = v - __uint_as_float(hi);
    asm("cvt.rna.tf32.f32 %0, %1;" : "=r"(lo) : "f"(r));
}

// ---------------- TF32x3 tile engine: 128x128 C tile, 256 threads ----------------
#define ST32 36
#define SMT32_FLOATS (4*128*ST32)
#define SMT32_BYTES  (SMT32_FLOATS*4)

__device__ __forceinline__ void t32_load_pre(const float* __restrict__ Ph,
                                             const float* __restrict__ Pl, int ldp,
                                             int kc, float* sh, float* sl, int tid) {
    #pragma unroll
    for (int it = 0; it < 4; it++) {
        int i = it*256 + tid;
        int row = i >> 3, kq = (i & 7)*4;
        uint4 h = *(const uint4*)(Ph + (size_t)row*ldp + kc + kq);
        uint4 l = *(const uint4*)(Pl + (size_t)row*ldp + kc + kq);
        *(uint4*)((uint32_t*)sh + row*ST32 + kq) = h;
        *(uint4*)((uint32_t*)sl + row*ST32 + kq) = l;
    }
}

__device__ __forceinline__ void t32_tile(const float* __restrict__ Ah_g, const float* __restrict__ Al_g, int lda,
                                         const float* __restrict__ Bh_g, const float* __restrict__ Bl_g, int ldb,
                                         int Kdim,
                                         float* sAh, float* sAl, float* sBh, float* sBl,
                                         int tid, float (&acc)[4][4][4]) {
    int warp = tid >> 5, lane = tid & 31;
    int g = lane >> 2, t = lane & 3;
    int wm = (warp >> 2)*64, wn = (warp & 3)*32;
    for (int kc = 0; kc < Kdim; kc += 32) {
        t32_load_pre(Ah_g, Al_g, lda, kc, sAh, sAl, tid);
        t32_load_pre(Bh_g, Bl_g, ldb, kc, sBh, sBl, tid);
        __syncthreads();
        #pragma unroll
        for (int ks = 0; ks < 32; ks += 8) {
            uint32_t ah[4][4], al[4][4];
            #pragma unroll
            for (int mt = 0; mt < 4; mt++) {
                const uint32_t* bh = (uint32_t*)sAh + (wm + mt*16)*ST32 + ks;
                const uint32_t* bl = (uint32_t*)sAl + (wm + mt*16)*ST32 + ks;
                ah[mt][0] = bh[g*ST32 + t];       ah[mt][1] = bh[(g+8)*ST32 + t];
                ah[mt][2] = bh[g*ST32 + t + 4];   ah[mt][3] = bh[(g+8)*ST32 + t + 4];
                al[mt][0] = bl[g*ST32 + t];       al[mt][1] = bl[(g+8)*ST32 + t];
                al[mt][2] = bl[g*ST32 + t + 4];   al[mt][3] = bl[(g+8)*ST32 + t + 4];
            }
            #pragma unroll
            for (int nt = 0; nt < 4; nt++) {
                const uint32_t* ph = (uint32_t*)sBh + (wn + nt*8 + g)*ST32 + ks;
                const uint32_t* pl = (uint32_t*)sBl + (wn + nt*8 + g)*ST32 + ks;
                uint32_t bh[2] = {ph[t], ph[t+4]};
                uint32_t bl[2] = {pl[t], pl[t+4]};
                #pragma unroll
                for (int mt = 0; mt < 4; mt++) {
                    mma1688(acc[mt][nt], ah[mt], bh);
                    mma1688(acc[mt][nt], ah[mt], bl);
                    mma1688(acc[mt][nt], al[mt], bh);
                }
            }
        }
        __syncthreads();
    }
}

__global__ void __launch_bounds__(256)
k_pair_t32(const float* __restrict__ fh, const float* __restrict__ fl, int Kdim,
           const float* __restrict__ xx, float* __restrict__ pd) {
    extern __shared__ float sm32[];
    float* sAh = sm32;
    float* sAl = sm32 + 128*ST32;
    float* sBh = sm32 + 2*128*ST32;
    float* sBl = sm32 + 3*128*ST32;
    int b = blockIdx.z;
    const float* Fh = fh + (size_t)b*NN*Kdim;
    const float* Fl = fl + (size_t)b*NN*Kdim;
    const float* xb = xx + b*NN;
    int n0 = blockIdx.x*128, m0 = blockIdx.y*128;
    int tid = threadIdx.x;
    float acc[4][4][4];
    #pragma unroll
    for (int i = 0; i < 4; i++)
        #pragma unroll
        for (int j = 0; j < 4; j++)
            #pragma unroll
            for (int r = 0; r < 4; r++) acc[i][j][r] = 0.f;

    t32_tile(Fh + (size_t)n0*Kdim, Fl + (size_t)n0*Kdim, Kdim,
             Fh + (size_t)m0*Kdim, Fl + (size_t)m0*Kdim, Kdim, Kdim,
             sAh, sAl, sBh, sBl, tid, acc);

    int warp = tid >> 5, lane = tid & 31;
    int g = lane >> 2, t = lane & 3;
    int wm = (warp >> 2)*64, wn = (warp & 3)*32;
    float* pb = pd + (size_t)b*NN*NN;
    #pragma unroll
    for (int mt = 0; mt < 4; mt++) {
        int n = n0 + wm + mt*16 + g;
        float xn0 = xb[n], xn1 = xb[n+8];
        #pragma unroll
        for (int nt = 0; nt < 4; nt++) {
            int col = m0 + wn + nt*8 + 2*t;
            float xm0 = xb[col], xm1 = xb[col+1];
            *(float2*)(pb + (size_t)n*NN + col) =
                make_float2(2.f*acc[mt][nt][0] - xn0 - xm0, 2.f*acc[mt][nt][1] - xn0 - xm1);
            *(float2*)(pb + (size_t)(n+8)*NN + col) =
                make_float2(2.f*acc[mt][nt][2] - xn1 - xm0, 2.f*acc[mt][nt][3] - xn1 - xm1);
        }
    }
}

__global__ void __launch_bounds__(256)
k_pq_t32(const float* __restrict__ fh, const float* __restrict__ fl, int lda,
         const float* __restrict__ wh, const float* __restrict__ wl, int ldb,
         float* __restrict__ Cout, int ldc, int Kdim) {
    extern __shared__ float sm32[];
    float* sAh = sm32;
    float* sAl = sm32 + 128*ST32;
    float* sBh = sm32 + 2*128*ST32;
    float* sBl = sm32 + 3*128*ST32;
    int m0 = blockIdx.x*128, o0 = blockIdx.y*128;
    int tid = threadIdx.x;
    float acc[4][4][4];
    #pragma unroll
    for (int i = 0; i < 4; i++)
        #pragma unroll
        for (int j = 0; j < 4; j++)
            #pragma unroll
            for (int r = 0; r < 4; r++) acc[i][j][r] = 0.f;

    t32_tile(fh + (size_t)m0*lda, fl + (size_t)m0*lda, lda,
             wh + (size_t)o0*ldb, wl + (size_t)o0*ldb, ldb, Kdim,
             sAh, sAl, sBh, sBl, tid, acc);

    int warp = tid >> 5, lane = tid & 31;
    int g = lane >> 2, t = lane & 3;
    int wm = (warp >> 2)*64, wn = (warp & 3)*32;
    #pragma unroll
    for (int mt = 0; mt < 4; mt++) {
        int r = m0 + wm + mt*16 + g;
        #pragma unroll
        for (int nt = 0; nt < 4; nt++) {
            int col = o0 + wn + nt*8 + 2*t;
            *(float2*)(Cout + (size_t)r*ldc + col)     = make_float2(acc[mt][nt][0], acc[mt][nt][1]);
            *(float2*)(Cout + (size_t)(r+8)*ldc + col) = make_float2(acc[mt][nt][2], acc[mt][nt][3]);
        }
    }
}

// ---------------- warp top-20 over 32x32 register tile ----------------
__device__ __forceinline__ void warp_top20(float (&vals)[32], int lane, int* orow) {
    unsigned rm = 0;
    float bv = vals[0]; int bslot = 0;
    #pragma unroll
    for (int j = 1; j < 32; j++) { float v = vals[j]; if (v > bv) { bv = v; bslot = j; } }
    for (int it = 0; it < KNN; it++) {
        float cv = bv;
        int ci = (bslot >= 0) ? (bslot*32 + lane) : 0x7fffffff;
        if (bslot < 0) cv = -INFINITY;
        #pragma unroll
        for (int s = 16; s > 0; s >>= 1) {
            float ov = __shfl_xor_sync(0xffffffffu, cv, s);
            int   oi = __shfl_xor_sync(0xffffffffu, ci, s);
            if (ov > cv || (ov == cv && oi < ci)) { cv = ov; ci = oi; }
        }
        if (lane == 0) orow[it] = ci;
        if ((ci & 31) == lane) {
            rm |= 1u << (ci >> 5);
            bv = -INFINITY; bslot = -1;
            #pragma unroll
            for (int j = 0; j < 32; j++) {
                if (!((rm >> j) & 1u)) {
                    float v = vals[j];
                    if (v > bv) { bv = v; bslot = j; }
                }
            }
        }
    }
}

// ---------------- kernels ----------------

__global__ void k_knn3(const float* __restrict__ x, int* __restrict__ idx,
                       float* __restrict__ sum, float* __restrict__ sumsq) {
    __shared__ float sx[NN], sy[NN], sz[NN];
    int b = blockIdx.y;
    const float* xb = x + (size_t)b*NN*3;
    int tid = threadIdx.x;
    if (blockIdx.x == 0 && b == 0) {
        for (int i = tid; i < 1024; i += 256) { sum[i] = 0.f; sumsq[i] = 0.f; }
    }
    for (int i = tid; i < NN; i += 256) {
        sx[i] = xb[i*3+0]; sy[i] = xb[i*3+1]; sz[i] = xb[i*3+2];
    }
    __syncthreads();
    int warp = tid >> 5, lane = tid & 31;
    int n = blockIdx.x*8 + warp;
    float xnx = sx[n], xny = sy[n], xnz = sz[n];
    float xxn = xnx*xnx; xxn += xny*xny; xxn += xnz*xnz;
    float vals[32];
    #pragma unroll
    for (int j = 0; j < 32; j++) {
        int m = j*32 + lane;
        float mx = sx[m], my = sy[m], mz = sz[m];
        float inner = xnx*mx; inner += xny*my; inner += xnz*mz;
        float xxm = mx*mx; xxm += my*my; xxm += mz*mz;
        vals[j] = 2.f*inner - xxn - xxm;
    }
    warp_top20(vals, lane, idx + (size_t)(b*NN + n)*KNN);
}

__global__ void k_topk_w(const float* __restrict__ pd, int* __restrict__ idx,
                         float* __restrict__ sum, float* __restrict__ sumsq) {
    int tid = threadIdx.x;
    if (blockIdx.x == 0) {
        for (int i = tid; i < 1024; i += 256) { sum[i] = 0.f; sumsq[i] = 0.f; }
    }
    int warp = tid >> 5;
    int lane = tid & 31;
    int row = blockIdx.x*8 + warp;
    const float* prow = pd + (size_t)row*NN;
    float vals[32];
    #pragma unroll
    for (int j = 0; j < 32; j++) vals[j] = prow[j*32 + lane];
    warp_top20(vals, lane, idx + (size_t)row*KNN);
}

__global__ void k_wpack(const float* __restrict__ W, int C, int O, float* __restrict__ wc) {
    int i = blockIdx.x*blockDim.x + threadIdx.x;
    if (i >= 2*O*C) return;
    int o2 = i / C, c = i - o2*C;
    if (o2 < O) wc[i] = W[(size_t)o2*2*C + c];
    else {
        int o = o2 - O;
        wc[i] = W[(size_t)o*2*C + C + c] - W[(size_t)o*2*C + c];
    }
}

__global__ void k_wpack_t32(const float* __restrict__ W, int C, int O,
                            float* __restrict__ wh, float* __restrict__ wl) {
    int i = blockIdx.x*blockDim.x + threadIdx.x;
    if (i >= 2*O*C) return;
    int o2 = i / C, c = i - o2*C;
    float v;
    if (o2 < O) v = W[(size_t)o2*2*C + c];
    else {
        int o = o2 - O;
        v = W[(size_t)o*2*C + C + c] - W[(size_t)o*2*C + c];
    }
    uint32_t hi, lo;
    split_tf32(v, hi, lo);
    wh[i] = __uint_as_float(hi);
    wl[i] = __uint_as_float(lo);
}

__global__ void k_cvt_w5(const float* __restrict__ W5, __nv_bfloat16* __restrict__ wh,
                         __nv_bfloat16* __restrict__ wl) {
    int i = blockIdx.x*blockDim.x + threadIdx.x;
    if (i >= 1024*512) return;
    float w = W5[i];
    __nv_bfloat16 h = __float2bfloat16(w);
    wh[i] = h;
    wl[i] = __float2bfloat16(w - __bfloat162float(h));
}

__global__ void k_sgemm(const float* __restrict__ A, int lda,
                        const float* __restrict__ Bw, int ldb,
                        float* __restrict__ Cout, int Kdim, int O) {
    __shared__ float As[16][65], Ws[16][65];
    int tx = threadIdx.x, ty = threadIdx.y;
    int tid = ty*16 + tx;
    int m0 = blockIdx.x*64, o0 = blockIdx.y*64;
    float acc[4][4];
    #pragma unroll
    for (int i = 0; i < 4; i++)
        #pragma unroll
        for (int j = 0; j < 4; j++) acc[i][j] = 0.f;
    for (int k0 = 0; k0 < Kdim; k0 += 16) {
        #pragma unroll
        for (int r = 0; r < 4; r++) {
            int i  = tid + r*256;
            int kk = i & 15, mm = i >> 4;
            As[kk][mm] = (k0+kk < Kdim) ? A[(size_t)(m0+mm)*lda + k0+kk] : 0.f;
            Ws[kk][mm] = (k0+kk < Kdim) ? Bw[(size_t)(o0+mm)*ldb + k0+kk] : 0.f;
        }
        __syncthreads();
        #pragma unroll
        for (int kk = 0; kk < 16; kk++) {
            float a[4], bfr[4];
            #pragma unroll
            for (int i = 0; i < 4; i++) a[i] = As[kk][ty*4 + i];
            #pragma unroll
            for (int j = 0; j < 4; j++) bfr[j] = Ws[kk][tx*4 + j];
            #pragma unroll
            for (int i = 0; i < 4; i++)
                #pragma unroll
                for (int j = 0; j < 4; j++) acc[i][j] += a[i]*bfr[j];
        }
        __syncthreads();
    }
    #pragma unroll
    for (int i = 0; i < 4; i++)
        #pragma unroll
        for (int j = 0; j < 4; j++)
            Cout[(size_t)(m0 + ty*4 + i)*O + o0 + tx*4 + j] = acc[i][j];
}

// ---------------- layer-5 tensor-core GEMM (bf16 hi/lo, pre-split) ----
#define KC5 64
#define SA5 72
#define SM5_TILE (128*SA5)
#define SM5_BYTES (4*SM5_TILE*2)

__global__ void __launch_bounds__(256, 1)
k_mma5(const __nv_bfloat16* __restrict__ c5h, const __nv_bfloat16* __restrict__ c5l,
       const __nv_bfloat16* __restrict__ w5h, const __nv_bfloat16* __restrict__ w5l,
       float* __restrict__ hout, float* __restrict__ sum, float* __restrict__ sumsq) {
    extern __shared__ __nv_bfloat16 sm[];
    __nv_bfloat16* Ah = sm;
    __nv_bfloat16* Al = sm + SM5_TILE;
    __nv_bfloat16* Bh = sm + 2*SM5_TILE;
    __nv_bfloat16* Bl = sm + 3*SM5_TILE;

    int tid = threadIdx.x;
    if (blockIdx.x == 0 && blockIdx.y == 0) {
        for (int i = tid; i < 1024; i += 256) { sum[i] = 0.f; sumsq[i] = 0.f; }
    }
    int warp = tid >> 5, lane = tid & 31;
    int g = lane >> 2, t = lane & 3;
    int m0 = blockIdx.x*128, o0 = blockIdx.y*128;
    int wm = (warp >> 2)*64;
    int wn = (warp & 3)*32;

    float acc[4][4][4];
    #pragma unroll
    for (int i = 0; i < 4; i++)
        #pragma unroll
        for (int j = 0; j < 4; j++)
            #pragma unroll
            for (int r = 0; r < 4; r++) acc[i][j][r] = 0.f;

    for (int kc = 0; kc < 512; kc += KC5) {
        #pragma unroll
        for (int it = 0; it < 4; it++) {
            int i = it*256 + tid;
            int row = i >> 3, kq = (i & 7)*8;
            uint4 h = *(const uint4*)(c5h + (size_t)(m0+row)*512 + kc + kq);
            uint4 l = *(const uint4*)(c5l + (size_t)(m0+row)*512 + kc + kq);
            *(uint4*)(Ah + row*SA5 + kq) = h;
            *(uint4*)(Al + row*SA5 + kq) = l;
        }
        #pragma unroll
        for (int it = 0; it < 4; it++) {
            int i = it*256 + tid;
            int row = i >> 3, kq = (i & 7)*8;
            uint4 h = *(const uint4*)(w5h + (size_t)(o0+row)*512 + kc + kq);
            uint4 l = *(const uint4*)(w5l + (size_t)(o0+row)*512 + kc + kq);
            *(uint4*)(Bh + row*SA5 + kq) = h;
            *(uint4*)(Bl + row*SA5 + kq) = l;
        }
        __syncthreads();

        #pragma unroll
        for (int ks = 0; ks < KC5; ks += 16) {
            uint32_t ah[4][4], al[4][4];
            #pragma unroll
            for (int mt = 0; mt < 4; mt++) {
                int r = wm + mt*16;
                ah[mt][0] = *(const uint32_t*)(Ah + (r+g  )*SA5 + ks + 2*t);
                ah[mt][1] = *(const uint32_t*)(Ah + (r+g+8)*SA5 + ks + 2*t);
                ah[mt][2] = *(const uint32_t*)(Ah + (r+g  )*SA5 + ks + 2*t + 8);
                ah[mt][3] = *(const uint32_t*)(Ah + (r+g+8)*SA5 + ks + 2*t + 8);
                al[mt][0] = *(const uint32_t*)(Al + (r+g  )*SA5 + ks + 2*t);
                al[mt][1] = *(const uint32_t*)(Al + (r+g+8)*SA5 + ks + 2*t);
                al[mt][2] = *(const uint32_t*)(Al + (r+g  )*SA5 + ks + 2*t + 8);
                al[mt][3] = *(const uint32_t*)(Al + (r+g+8)*SA5 + ks + 2*t + 8);
            }
            #pragma unroll
            for (int nt = 0; nt < 4; nt++) {
                int nr = wn + nt*8 + g;
                uint32_t bh[2], bl[2];
                bh[0] = *(const uint32_t*)(Bh + nr*SA5 + ks + 2*t);
                bh[1] = *(const uint32_t*)(Bh + nr*SA5 + ks + 2*t + 8);
                bl[0] = *(const uint32_t*)(Bl + nr*SA5 + ks + 2*t);
                bl[1] = *(const uint32_t*)(Bl + nr*SA5 + ks + 2*t + 8);
                #pragma unroll
                for (int mt = 0; mt < 4; mt++) {
                    mma16816(acc[mt][nt], ah[mt], bh);
                    mma16816(acc[mt][nt], ah[mt], bl);
                    mma16816(acc[mt][nt], al[mt], bh);
                }
            }
        }
        __syncthreads();
    }

    #pragma unroll
    for (int mt = 0; mt < 4; mt++) {
        int r0g = m0 + wm + mt*16 + g;
        #pragma unroll
        for (int nt = 0; nt < 4; nt++) {
            int col = o0 + wn + nt*8 + 2*t;
            *(float2*)(hout + (size_t)r0g*1024 + col)     = make_float2(acc[mt][nt][0], acc[mt][nt][1]);
            *(float2*)(hout + (size_t)(r0g+8)*1024 + col) = make_float2(acc[mt][nt][2], acc[mt][nt][3]);
        }
    }
}

// gather: 256 threads, float4 column groups, 32 rows/block
__global__ void __launch_bounds__(256)
k_gather(const float* __restrict__ pq, const int* __restrict__ idx,
         float* __restrict__ hmax,
         float* __restrict__ sum, float* __restrict__ sumsq, int O) {
    int tid = threadIdx.x;
    int oq4 = O >> 2;            // col groups (16/32/64)
    int nr = 256/oq4;            // parallel rows (16/8/4)
    int rsub = tid / oq4;
    int cg = tid - rsub*oq4;
    int r0 = blockIdx.x*32;
    int b = r0 >> 10;
    int ld = 2*O;
    __shared__ int sidx[32*KNN];
    __shared__ float4 ssum[256], ssq[256];
    for (int i = tid; i < 32*KNN; i += 256) sidx[i] = idx[(size_t)r0*KNN + i];
    __syncthreads();
    const float* pb = pq + (size_t)b*NN*ld;
    float4 s  = make_float4(0.f, 0.f, 0.f, 0.f);
    float4 s2 = make_float4(0.f, 0.f, 0.f, 0.f);
    for (int n = rsub; n < 32; n += nr) {
        int row = r0 + n;
        float4 cq = *(const float4*)(pq + (size_t)row*ld + O + cg*4);
        float4 mx = make_float4(-INFINITY, -INFINITY, -INFINITY, -INFINITY);
        #pragma unroll
        for (int k = 0; k < KNN; k++) {
            float4 v = *(const float4*)(pb + (size_t)sidx[n*KNN + k]*ld + cg*4);
            mx.x = fmaxf(mx.x, v.x); mx.y = fmaxf(mx.y, v.y);
            mx.z = fmaxf(mx.z, v.z); mx.w = fmaxf(mx.w, v.w);
            float hx = v.x + cq.x, hy = v.y + cq.y, hz = v.z + cq.z, hw = v.w + cq.w;
            s.x += hx; s.y += hy; s.z += hz; s.w += hw;
            s2.x += hx*hx; s2.y += hy*hy; s2.z += hz*hz; s2.w += hw*hw;
        }
        *(float4*)(hmax + (size_t)row*O + cg*4) =
            make_float4(mx.x + cq.x, mx.y + cq.y, mx.z + cq.z, mx.w + cq.w);
    }
    ssum[tid] = s; ssq[tid] = s2;
    __syncthreads();
    if (rsub == 0) {
        for (int j = 1; j < nr; j++) {
            float4 a = ssum[j*oq4 + cg], q = ssq[j*oq4 + cg];
            s.x += a.x; s.y += a.y; s.z += a.z; s.w += a.w;
            s2.x += q.x; s2.y += q.y; s2.z += q.z; s2.w += q.w;
        }
        atomicAdd(&sum[cg*4+0], s.x);  atomicAdd(&sum[cg*4+1], s.y);
        atomicAdd(&sum[cg*4+2], s.z);  atomicAdd(&sum[cg*4+3], s.w);
        atomicAdd(&sumsq[cg*4+0], s2.x); atomicAdd(&sumsq[cg*4+1], s2.y);
        atomicAdd(&sumsq[cg*4+2], s2.z); atomicAdd(&sumsq[cg*4+3], s2.w);
    }
}

// warp-per-row BN + lrelu; emits bf16 split into cat arrays (+ optional tf32 split + xx)
__global__ void k_bn_f(const float* __restrict__ hmax, const float* __restrict__ sum,
                       const float* __restrict__ sumsq,
                       const float* __restrict__ gamma, const float* __restrict__ beta,
                       __nv_bfloat16* __restrict__ c5h, __nv_bfloat16* __restrict__ c5l, int coff,
                       float* __restrict__ fh, float* __restrict__ fl, float* __restrict__ xx,
                       int O, float invCnt, int wantNext) {
    int warp = threadIdx.x >> 5, lane = threadIdx.x & 31;
    int row = blockIdx.x*8 + warp;
    float s2 = 0.f;
    for (int o = lane; o < O; o += 32) {
        float mean = sum[o]*invCnt;
        float var  = sumsq[o]*invCnt - mean*mean;
        float hn = (hmax[(size_t)row*O + o] - mean)*rsqrtf(var + EPS)*gamma[o] + beta[o];
        hn = hn >= 0.f ? hn : NEG_SLOPE*hn;
        __nv_bfloat16 h = __float2bfloat16(hn);
        c5h[(size_t)row*512 + coff + o] = h;
        c5l[(size_t)row*512 + coff + o] = __float2bfloat16(hn - __bfloat162float(h));
        if (wantNext) {
            uint32_t thi, tlo;
            split_tf32(hn, thi, tlo);
            fh[(size_t)row*O + o] = __uint_as_float(thi);
            fl[(size_t)row*O + o] = __uint_as_float(tlo);
            s2 += hn*hn;
        }
    }
    if (wantNext) {
        #pragma unroll
        for (int s = 16; s > 0; s >>= 1) s2 += __shfl_xor_sync(0xffffffffu, s2, s);
        if (lane == 0) xx[row] = s2;
    }
}

// layer-5 reduction: partial over 128 n-rows per block (grid z = 8)
__global__ void k_reduce5(const float* __restrict__ h, float* __restrict__ redp,
                          float* __restrict__ sum, float* __restrict__ sumsq) {
    int b = blockIdx.x;
    int o = blockIdx.y*256 + threadIdx.x;
    int z = blockIdx.z;
    const float* hb = h + ((size_t)b*NN + z*128)*1024;
    float mx = -INFINITY, s = 0.f, s2 = 0.f;
    #pragma unroll 4
    for (int n = 0; n < 128; n++) {
        float v = hb[(size_t)n*1024 + o];
        mx = fmaxf(mx, v); s += v; s2 += v*v;
    }
    redp[((size_t)b*8 + z)*1024 + o] = mx;
    atomicAdd(&sum[o], s);
    atomicAdd(&sumsq[o], s2);
}

__global__ void k_final(const float* __restrict__ redp, const float* __restrict__ sum,
                        const float* __restrict__ sumsq,
                        const float* __restrict__ gamma, const float* __restrict__ beta,
                        float* __restrict__ out) {
    int e = blockIdx.x*blockDim.x + threadIdx.x;   // 32768
    int b = e >> 10, o = e & 1023;
    float mx = -INFINITY;
    #pragma unroll
    for (int z = 0; z < 8; z++) mx = fmaxf(mx, redp[((size_t)b*8 + z)*1024 + o]);
    float invCnt = 1.f/32768.f;
    float mean = sum[o]*invCnt;
    float var  = sumsq[o]*invCnt - mean*mean;
    float hn = (mx - mean)*rsqrtf(var + EPS)*gamma[o] + beta[o];
    out[e] = hn >= 0.f ? hn : NEG_SLOPE*hn;
}

// ---------------- host driver ----------------

extern "C" void kernel_launch(void* const* d_in, const int* in_sizes, int n_in,
                              void* d_out, int out_size) {
    const float* x = (const float*)d_in[0];
    const float* W[5]; const float* ga[5]; const float* be[5];
    for (int i = 0; i < 5; i++) {
        W[i]  = (const float*)d_in[1 + 3*i];
        ga[i] = (const float*)d_in[2 + 3*i];
        be[i] = (const float*)d_in[3 + 3*i];
    }

    float *pd, *pq, *hmax, *wc, *wch, *wcl, *fh, *fl, *xx, *sum, *sumsq, *redp;
    __nv_bfloat16 *c5h, *c5l, *w5h, *w5l;
    int *idx;
    cudaGetSymbolAddress((void**)&pd,    g_pd);
    cudaGetSymbolAddress((void**)&idx,   g_idx);
    cudaGetSymbolAddress((void**)&pq,    g_pq);
    cudaGetSymbolAddress((void**)&hmax,  g_hmax);
    cudaGetSymbolAddress((void**)&wc,    g_wc);
    cudaGetSymbolAddress((void**)&wch,   g_wch);
    cudaGetSymbolAddress((void**)&wcl,   g_wcl);
    cudaGetSymbolAddress((void**)&fh,    g_fh);
    cudaGetSymbolAddress((void**)&fl,    g_fl);
    cudaGetSymbolAddress((void**)&xx,    g_xx);
    cudaGetSymbolAddress((void**)&sum,   g_sum);
    cudaGetSymbolAddress((void**)&sumsq, g_sumsq);
    cudaGetSymbolAddress((void**)&redp,  g_redp);
    cudaGetSymbolAddress((void**)&c5h,   g_c5h);
    cudaGetSymbolAddress((void**)&c5l,   g_c5l);
    cudaGetSymbolAddress((void**)&w5h,   g_w5h);
    cudaGetSymbolAddress((void**)&w5l,   g_w5l);

    cudaFuncSetAttribute(k_mma5, cudaFuncAttributeMaxDynamicSharedMemorySize, SM5_BYTES);
    cudaFuncSetAttribute(k_pair_t32, cudaFuncAttributeMaxDynamicSharedMemorySize, SMT32_BYTES);
    cudaFuncSetAttribute(k_pq_t32, cudaFuncAttributeMaxDynamicSharedMemorySize, SMT32_BYTES);

    float* wch2 = wch;           float* wcl2 = wcl;
    float* wch3 = wch + 8192;    float* wcl3 = wcl + 8192;
    float* wch4 = wch + 24576;   float* wcl4 = wcl + 24576;

    const float invKN = 1.f/((float)RTOT*KNN);

    // ---- layer 1 (C=3) ----
    k_wpack<<<(2*64*3 + 255)/256, 256>>>(W[0], 3, 64, wc);
    k_knn3<<<dim3(128, 32), 256>>>(x, idx, sum, sumsq);
    k_sgemm<<<dim3(RTOT/64, 2), dim3(16,16)>>>(x, 3, wc, 3, pq, 3, 128);
    k_gather<<<RTOT/32, 256>>>(pq, idx, hmax, sum, sumsq, 64);
    k_bn_f<<<RTOT/8, 256>>>(hmax, sum, sumsq, ga[0], be[0],
                            c5h, c5l, 0, fh, fl, xx, 64, invKN, 1);

    // ---- layer 2 ----
    k_pair_t32<<<dim3(8, 8, 32), 256, SMT32_BYTES>>>(fh, fl, 64, xx, pd);
    k_wpack_t32<<<(2*64*64  + 255)/256, 256>>>(W[1], 64,  64,  wch2, wcl2);
    k_wpack_t32<<<(2*128*64 + 255)/256, 256>>>(W[2], 64,  128, wch3, wcl3);
    k_wpack_t32<<<(2*256*128+ 255)/256, 256>>>(W[3], 128, 256, wch4, wcl4);
    k_cvt_w5<<<(1024*512 + 255)/256, 256>>>(W[4], w5h, w5l);
    k_topk_w<<<RTOT/8, 256>>>(pd, idx, sum, sumsq);
    k_pq_t32<<<dim3(RTOT/128, 1), 256, SMT32_BYTES>>>(fh, fl, 64, wch2, wcl2, 64, pq, 128, 64);
    k_gather<<<RTOT/32, 256>>>(pq, idx, hmax, sum, sumsq, 64);
    k_bn_f<<<RTOT/8, 256>>>(hmax, sum, sumsq, ga[1], be[1],
                            c5h, c5l, 64, fh, fl, xx, 64, invKN, 1);

    // ---- layer 3 ----
    k_pair_t32<<<dim3(8, 8, 32), 256, SMT32_BYTES>>>(fh, fl, 64, xx, pd);
    k_topk_w<<<RTOT/8, 256>>>(pd, idx, sum, sumsq);
    k_pq_t32<<<dim3(RTOT/128, 2), 256, SMT32_BYTES>>>(fh, fl, 64, wch3, wcl3, 64, pq, 256, 64);
    k_gather<<<RTOT/32, 256>>>(pq, idx, hmax, sum, sumsq, 128);
    k_bn_f<<<RTOT/8, 256>>>(hmax, sum, sumsq, ga[2], be[2],
                            c5h, c5l, 128, fh, fl, xx, 128, invKN, 1);

    // ---- layer 4 ----
    k_pair_t32<<<dim3(8, 8, 32), 256, SMT32_BYTES>>>(fh, fl, 128, xx, pd);
    k_topk_w<<<RTOT/8, 256>>>(pd, idx, sum, sumsq);
    k_pq_t32<<<dim3(RTOT/128, 4), 256, SMT32_BYTES>>>(fh, fl, 128, wch4, wcl4, 128, pq, 512, 128);
    k_gather<<<RTOT/32, 256>>>(pq, idx, hmax, sum, sumsq, 256);
    k_bn_f<<<RTOT/8, 256>>>(hmax, sum, sumsq, ga[3], be[3],
                            c5h, c5l, 256, fh, fl, xx, 256, invKN, 0);

    // ---- layer 5 ----
    k_mma5<<<dim3(RTOT/128, 1024/128), 256, SM5_BYTES>>>(c5h, c5l, w5h, w5l, pd, sum, sumsq);
    k_reduce5<<<dim3(BB, 4, 8), 256>>>(pd, redp, sum, sumsq);
    k_final<<<RTOT/256, 256>>>(redp, sum, sumsq, ga[4], be[4], (float*)d_out);
}